// round 1
// baseline (speedup 1.0000x reference)
#include <cuda_runtime.h>
#include <math.h>

#define B_   2
#define S_   2048
#define D_   2048
#define H_   16
#define KV_  8
#define DH_  128

// ---------------- persistent scratch (no allocation allowed) ----------------
__device__ float  g_qkv [B_ * S_ * 4096];        // q|k|v concatenated, [B*S, 4096]
__device__ float  g_q   [B_ * H_  * S_ * DH_];   // [B,H,S,128]
__device__ float  g_k   [B_ * KV_ * S_ * DH_];   // [B,KV,S,128]
__device__ float  g_v   [B_ * KV_ * S_ * DH_];   // [B,KV,S,128]
__device__ float  g_attn[B_ * S_ * D_];          // [B,S,H*128]
__device__ float2 g_rope[S_ * 64];               // cos/sin per (s, freq)

// ---------------- RoPE table (double precision to match true values) --------
__global__ void rope_init_kernel(float2* __restrict__ tab) {
    int idx = blockIdx.x * blockDim.x + threadIdx.x;
    if (idx >= S_ * 64) return;
    int s = idx >> 6, j = idx & 63;
    // inv_freq = 10000^(-j/64)
    double inv = exp(-(double)j * (9.210340371976184 / 64.0));
    double ang = (double)s * inv;
    tab[idx] = make_float2((float)cos(ang), (float)sin(ang));
}

// ---------------- SGEMM:  C[m, cofs+n] = sum_k A[m,k] * Bm[n,k] -------------
// A: [M, K] row-major, Bm: [N, K] row-major (i.e. C = A @ Bm^T)
#define GBM 128
#define GBN 128
#define GBK 16

__global__ __launch_bounds__(256) void gemm_nt(
    const float* __restrict__ A, const float* __restrict__ Bm,
    float* __restrict__ C, int K, int ldc, int cofs)
{
    __shared__ float As[GBK][GBM + 4];
    __shared__ float Bs[GBK][GBN + 4];
    const int tid  = threadIdx.x;
    const int m0   = blockIdx.y * GBM;
    const int n0   = blockIdx.x * GBN;
    const int lrow = tid >> 2;          // 0..63
    const int lcol = (tid & 3) << 2;    // 0,4,8,12
    const int trow = (tid >> 4) << 3;   // 0..120
    const int tcol = (tid & 15) << 3;   // 0..120

    float acc[8][8];
    #pragma unroll
    for (int i = 0; i < 8; ++i)
        #pragma unroll
        for (int j = 0; j < 8; ++j) acc[i][j] = 0.f;

    const float* Aptr = A  + (size_t)(m0 + lrow) * K + lcol;
    const float* Bptr = Bm + (size_t)(n0 + lrow) * K + lcol;

    for (int k0 = 0; k0 < K; k0 += GBK) {
        #pragma unroll
        for (int i = 0; i < 2; ++i) {
            float4 va = *(const float4*)(Aptr + (size_t)(i * 64) * K + k0);
            As[lcol + 0][lrow + i * 64] = va.x;
            As[lcol + 1][lrow + i * 64] = va.y;
            As[lcol + 2][lrow + i * 64] = va.z;
            As[lcol + 3][lrow + i * 64] = va.w;
            float4 vb = *(const float4*)(Bptr + (size_t)(i * 64) * K + k0);
            Bs[lcol + 0][lrow + i * 64] = vb.x;
            Bs[lcol + 1][lrow + i * 64] = vb.y;
            Bs[lcol + 2][lrow + i * 64] = vb.z;
            Bs[lcol + 3][lrow + i * 64] = vb.w;
        }
        __syncthreads();
        #pragma unroll
        for (int kk = 0; kk < GBK; ++kk) {
            float af[8], bf[8];
            #pragma unroll
            for (int i = 0; i < 8; ++i) af[i] = As[kk][trow + i];
            #pragma unroll
            for (int j = 0; j < 8; ++j) bf[j] = Bs[kk][tcol + j];
            #pragma unroll
            for (int i = 0; i < 8; ++i)
                #pragma unroll
                for (int j = 0; j < 8; ++j)
                    acc[i][j] = fmaf(af[i], bf[j], acc[i][j]);
        }
        __syncthreads();
    }
    #pragma unroll
    for (int i = 0; i < 8; ++i) {
        float* crow = C + (size_t)(m0 + trow + i) * ldc + cofs + n0 + tcol;
        #pragma unroll
        for (int j = 0; j < 8; j += 4) {
            float4 v = make_float4(acc[i][j], acc[i][j+1], acc[i][j+2], acc[i][j+3]);
            *(float4*)(crow + j) = v;
        }
    }
}

// ---------------- canon conv + RMSNorm + RoPE + relayout ---------------------
__global__ __launch_bounds__(256) void postproc_kernel(
    const float* __restrict__ qkv,
    const float* __restrict__ cwq, const float* __restrict__ cwk, const float* __restrict__ cwv,
    const float* __restrict__ qnw, const float* __restrict__ knw,
    const float2* __restrict__ rope,
    float* __restrict__ qo, float* __restrict__ ko, float* __restrict__ vo)
{
    __shared__ float sm[4096];
    const int s   = blockIdx.x;
    const int b   = blockIdx.y;
    const int tid = threadIdx.x;
    const float* row0 = qkv + ((size_t)b * S_ + s) * 4096;

    // causal depthwise conv (K=4) + residual: out = x*(1+w0) + w1*x[-1] + w2*x[-2] + w3*x[-3]
    for (int c = tid; c < 4096; c += 256) {
        const float* cw;
        if (c < 2048)       cw = cwq + (size_t)c * 4;
        else if (c < 3072)  cw = cwk + (size_t)(c - 2048) * 4;
        else                cw = cwv + (size_t)(c - 3072) * 4;
        float x0  = row0[c];
        float acc = x0 + cw[0] * x0;
        if (s >= 1) acc = fmaf(cw[1], row0[c - 4096],     acc);
        if (s >= 2) acc = fmaf(cw[2], row0[c - 2 * 4096], acc);
        if (s >= 3) acc = fmaf(cw[3], row0[c - 3 * 4096], acc);
        sm[c] = acc;
    }
    __syncthreads();

    // V: plain copy (no norm / rope)
    for (int idx = tid; idx < KV_ * DH_; idx += 256) {
        int kvh = idx >> 7, d = idx & 127;
        vo[(((size_t)b * KV_ + kvh) * S_ + s) * DH_ + d] = sm[3072 + idx];
    }

    // Q heads (16) + K heads (8): RMSNorm + RoPE, one warp per head
    const int warp = tid >> 5, lane = tid & 31;
    const float2 cs0 = rope[(size_t)s * 64 + lane];
    const float2 cs1 = rope[(size_t)s * 64 + lane + 32];
    for (int h24 = warp; h24 < 24; h24 += 8) {
        bool isq  = h24 < 16;
        int  base = isq ? h24 * 128 : 2048 + (h24 - 16) * 128;
        float v0 = sm[base + lane];
        float v1 = sm[base + lane + 32];
        float v2 = sm[base + lane + 64];
        float v3 = sm[base + lane + 96];
        float ss = v0*v0 + v1*v1 + v2*v2 + v3*v3;
        #pragma unroll
        for (int o = 16; o > 0; o >>= 1) ss += __shfl_xor_sync(0xffffffffu, ss, o);
        float r = rsqrtf(ss * (1.0f / 128.0f) + 1e-6f);
        const float* nw = isq ? qnw : knw;
        float a0 = v0 * r * nw[lane];
        float a1 = v1 * r * nw[lane + 32];
        float a2 = v2 * r * nw[lane + 64];
        float a3 = v3 * r * nw[lane + 96];
        // RoPE pairs: (j, j+64) for j = lane and j = lane+32
        float o_lo0 = a0 * cs0.x - a2 * cs0.y;
        float o_hi0 = a2 * cs0.x + a0 * cs0.y;
        float o_lo1 = a1 * cs1.x - a3 * cs1.y;
        float o_hi1 = a3 * cs1.x + a1 * cs1.y;
        float* dst;
        if (isq) dst = qo + (((size_t)b * H_  + h24)        * S_ + s) * DH_;
        else     dst = ko + (((size_t)b * KV_ + (h24 - 16)) * S_ + s) * DH_;
        dst[lane]      = o_lo0;
        dst[lane + 32] = o_lo1;
        dst[lane + 64] = o_hi0;
        dst[lane + 96] = o_hi1;
    }
}

// ---------------- causal flash attention (fp32), BM=BN=64 --------------------
__global__ __launch_bounds__(256) void flash_attn_kernel(
    const float* __restrict__ Q, const float* __restrict__ Kg,
    const float* __restrict__ Vg, float* __restrict__ O)
{
    extern __shared__ float smem[];
    float* Qs = smem;                 // [128][65]  (Qs[k][r], transposed)
    float* Ks = Qs + 128 * 65;        // [128][65]
    float* Vs = Ks + 128 * 65;        // [64][128]  row-major
    float* Ps = Vs + 64 * 128;        // [64][65]   (Ps[j][r], transposed)

    const int q0  = blockIdx.x * 64;
    const int h   = blockIdx.y;
    const int b   = blockIdx.z;
    const int tid = threadIdx.x;
    const int ty  = tid >> 4, tx = tid & 15;
    const int trow = ty * 4;
    const float scale = 0.08838834764831845f;   // 1/sqrt(128)

    const float* Qbase = Q  + (((size_t)b * H_  + h)        * S_ + q0) * DH_;
    const float* Kbase = Kg + (((size_t)b * KV_ + (h >> 1)) * S_)      * DH_;
    const float* Vbase = Vg + (((size_t)b * KV_ + (h >> 1)) * S_)      * DH_;

    // load Q transposed
    for (int idx = tid; idx < 64 * 32; idx += 256) {
        int r = idx >> 5, c4 = idx & 31;
        float4 v = *(const float4*)(Qbase + (size_t)r * 128 + c4 * 4);
        Qs[(c4 * 4 + 0) * 65 + r] = v.x;
        Qs[(c4 * 4 + 1) * 65 + r] = v.y;
        Qs[(c4 * 4 + 2) * 65 + r] = v.z;
        Qs[(c4 * 4 + 3) * 65 + r] = v.w;
    }

    float acc[4][8];
    float m_i[4], l_i[4];
    #pragma unroll
    for (int i = 0; i < 4; ++i) {
        m_i[i] = -1e30f; l_i[i] = 0.f;
        #pragma unroll
        for (int c = 0; c < 8; ++c) acc[i][c] = 0.f;
    }

    const int nblocks = (q0 >> 6) + 1;
    for (int jb = 0; jb < nblocks; ++jb) {
        const int j0 = jb * 64;
        __syncthreads();
        for (int idx = tid; idx < 64 * 32; idx += 256) {
            int r = idx >> 5, c4 = idx & 31;
            float4 v = *(const float4*)(Kbase + (size_t)(j0 + r) * 128 + c4 * 4);
            Ks[(c4 * 4 + 0) * 65 + r] = v.x;
            Ks[(c4 * 4 + 1) * 65 + r] = v.y;
            Ks[(c4 * 4 + 2) * 65 + r] = v.z;
            Ks[(c4 * 4 + 3) * 65 + r] = v.w;
            float4 w = *(const float4*)(Vbase + (size_t)(j0 + r) * 128 + c4 * 4);
            *(float4*)(Vs + r * 128 + c4 * 4) = w;
        }
        __syncthreads();

        // S = Q K^T  (each thread: 4x4)
        float sv[4][4];
        #pragma unroll
        for (int i = 0; i < 4; ++i)
            #pragma unroll
            for (int j = 0; j < 4; ++j) sv[i][j] = 0.f;
        #pragma unroll 4
        for (int k = 0; k < 128; ++k) {
            float af[4], bf[4];
            #pragma unroll
            for (int i = 0; i < 4; ++i) af[i] = Qs[k * 65 + trow + i];
            #pragma unroll
            for (int j = 0; j < 4; ++j) bf[j] = Ks[k * 65 + tx * 4 + j];
            #pragma unroll
            for (int i = 0; i < 4; ++i)
                #pragma unroll
                for (int j = 0; j < 4; ++j)
                    sv[i][j] = fmaf(af[i], bf[j], sv[i][j]);
        }

        const bool diag = (jb == nblocks - 1);
        #pragma unroll
        for (int i = 0; i < 4; ++i) {
            const int qrow = q0 + trow + i;
            #pragma unroll
            for (int j = 0; j < 4; ++j) {
                float x = sv[i][j] * scale;
                if (diag && (j0 + tx * 4 + j > qrow)) x = -1e30f;
                sv[i][j] = x;
            }
        }

        // online softmax (rows owned by 16 lanes sharing ty)
        #pragma unroll
        for (int i = 0; i < 4; ++i) {
            float mx = fmaxf(fmaxf(sv[i][0], sv[i][1]), fmaxf(sv[i][2], sv[i][3]));
            #pragma unroll
            for (int o = 8; o > 0; o >>= 1) mx = fmaxf(mx, __shfl_xor_sync(0xffffffffu, mx, o));
            float mnew  = fmaxf(m_i[i], mx);
            float alpha = __expf(m_i[i] - mnew);
            float rs = 0.f;
            #pragma unroll
            for (int j = 0; j < 4; ++j) {
                float p = __expf(sv[i][j] - mnew);
                sv[i][j] = p;
                rs += p;
            }
            #pragma unroll
            for (int o = 8; o > 0; o >>= 1) rs += __shfl_xor_sync(0xffffffffu, rs, o);
            l_i[i] = l_i[i] * alpha + rs;
            m_i[i] = mnew;
            #pragma unroll
            for (int c = 0; c < 8; ++c) acc[i][c] *= alpha;
            #pragma unroll
            for (int j = 0; j < 4; ++j) Ps[(tx * 4 + j) * 65 + trow + i] = sv[i][j];
        }
        __syncthreads();

        // acc += P V  (each thread: 4 rows x 8 cols)
        #pragma unroll 2
        for (int j = 0; j < 64; ++j) {
            float pf[4];
            #pragma unroll
            for (int i = 0; i < 4; ++i) pf[i] = Ps[j * 65 + trow + i];
            float4 vlo = *(const float4*)(Vs + j * 128 + tx * 8);
            float4 vhi = *(const float4*)(Vs + j * 128 + tx * 8 + 4);
            float vf[8] = {vlo.x, vlo.y, vlo.z, vlo.w, vhi.x, vhi.y, vhi.z, vhi.w};
            #pragma unroll
            for (int i = 0; i < 4; ++i)
                #pragma unroll
                for (int c = 0; c < 8; ++c)
                    acc[i][c] = fmaf(pf[i], vf[c], acc[i][c]);
        }
    }

    // epilogue: O[b, s, h*128 + c] = acc / l
    #pragma unroll
    for (int i = 0; i < 4; ++i) {
        float inv = 1.f / l_i[i];
        float* orow = O + ((size_t)b * S_ + q0 + trow + i) * D_ + h * DH_ + tx * 8;
        #pragma unroll
        for (int c = 0; c < 4; ++c) orow[c] = acc[i][c] * inv;
        #pragma unroll
        for (int c = 4; c < 8; ++c) orow[c] = acc[i][c] * inv;
    }
}

// ---------------- launch ----------------
extern "C" void kernel_launch(void* const* d_in, const int* in_sizes, int n_in,
                              void* d_out, int out_size)
{
    const float* hidden = (const float*)d_in[0];
    const float* Wq     = (const float*)d_in[1];
    const float* Wk     = (const float*)d_in[2];
    const float* Wv     = (const float*)d_in[3];
    const float* Wo     = (const float*)d_in[4];
    const float* cwq    = (const float*)d_in[5];
    const float* cwk    = (const float*)d_in[6];
    const float* cwv    = (const float*)d_in[7];
    const float* qnw    = (const float*)d_in[8];
    const float* knw    = (const float*)d_in[9];
    float* out = (float*)d_out;

    float  *qkv, *q, *k, *v, *attn;
    float2 *rope;
    cudaGetSymbolAddress((void**)&qkv,  g_qkv);
    cudaGetSymbolAddress((void**)&q,    g_q);
    cudaGetSymbolAddress((void**)&k,    g_k);
    cudaGetSymbolAddress((void**)&v,    g_v);
    cudaGetSymbolAddress((void**)&attn, g_attn);
    cudaGetSymbolAddress((void**)&rope, g_rope);

    // RoPE table
    rope_init_kernel<<<(S_ * 64 + 255) / 256, 256>>>(rope);

    // QKV projections (C = hidden @ W^T), concatenated into g_qkv
    gemm_nt<<<dim3(D_  / GBN, (B_ * S_) / GBM), 256>>>(hidden, Wq, qkv, D_, 4096, 0);
    gemm_nt<<<dim3(1024 / GBN, (B_ * S_) / GBM), 256>>>(hidden, Wk, qkv, D_, 4096, 2048);
    gemm_nt<<<dim3(1024 / GBN, (B_ * S_) / GBM), 256>>>(hidden, Wv, qkv, D_, 4096, 3072);

    // canon + rmsnorm + rope + relayout
    postproc_kernel<<<dim3(S_, B_), 256>>>(qkv, cwq, cwk, cwv, qnw, knw, rope, q, k, v);

    // flash attention
    size_t shmem = (size_t)(128 * 65 + 128 * 65 + 64 * 128 + 64 * 65) * sizeof(float);
    cudaFuncSetAttribute(flash_attn_kernel,
                         cudaFuncAttributeMaxDynamicSharedMemorySize, (int)shmem);
    flash_attn_kernel<<<dim3(S_ / 64, H_, B_), 256, shmem>>>(q, k, v, attn);

    // output projection
    gemm_nt<<<dim3(D_ / GBN, (B_ * S_) / GBM), 256>>>(attn, Wo, out, D_, D_, 0);
}

// round 3
// speedup vs baseline: 1.6493x; 1.6493x over previous
#include <cuda_runtime.h>
#include <math.h>
#include <stdint.h>

#define B_   2
#define S_   2048
#define D_   2048
#define H_   16
#define KV_  8
#define DH_  128

// ---------------- persistent scratch ----------------
__device__ float  g_qkv [B_ * S_ * 4096];        // q|k|v concatenated, [B*S, 4096]
__device__ float  g_q   [B_ * H_  * S_ * DH_];
__device__ float  g_k   [B_ * KV_ * S_ * DH_];
__device__ float  g_v   [B_ * KV_ * S_ * DH_];
__device__ float  g_attn[B_ * S_ * D_];
__device__ float2 g_rope[S_ * 64];

// ---------------- PTX helpers (sm_80-era only; no tcgen05 on this toolchain) ----
__device__ __forceinline__ uint32_t smem_u32(const void* p) {
    uint32_t a;
    asm("{ .reg .u64 t; cvta.to.shared.u64 t, %1; cvt.u32.u64 %0, t; }" : "=r"(a) : "l"(p));
    return a;
}
__device__ __forceinline__ void cp_async16(uint32_t saddr, const void* gaddr) {
    asm volatile("cp.async.cg.shared.global [%0], [%1], 16;" :: "r"(saddr), "l"(gaddr));
}
__device__ __forceinline__ void cp_commit() {
    asm volatile("cp.async.commit_group;" ::: "memory");
}
template <int N>
__device__ __forceinline__ void cp_wait() {
    asm volatile("cp.async.wait_group %0;" :: "n"(N) : "memory");
}
__device__ __forceinline__ uint32_t f2tf32(float x) {
    uint32_t r;
    asm("cvt.rna.tf32.f32 %0, %1;" : "=r"(r) : "f"(x));
    return r;
}
__device__ __forceinline__ void mma_tf32(float* c, const uint32_t* a, const uint32_t* b) {
    asm volatile(
        "mma.sync.aligned.m16n8k8.row.col.f32.tf32.tf32.f32 "
        "{%0,%1,%2,%3}, {%4,%5,%6,%7}, {%8,%9}, {%0,%1,%2,%3};"
        : "+f"(c[0]), "+f"(c[1]), "+f"(c[2]), "+f"(c[3])
        : "r"(a[0]), "r"(a[1]), "r"(a[2]), "r"(a[3]), "r"(b[0]), "r"(b[1]));
}

// ---------------- RoPE table ----------------
__global__ void rope_init_kernel(float2* __restrict__ tab) {
    int idx = blockIdx.x * blockDim.x + threadIdx.x;
    if (idx >= S_ * 64) return;
    int s = idx >> 6, j = idx & 63;
    double inv = exp(-(double)j * (9.210340371976184 / 64.0));
    double ang = (double)s * inv;
    tab[idx] = make_float2((float)cos(ang), (float)sin(ang));
}

// ---------------- mma.sync tf32 GEMM:  C[m, n] = sum_k A[m,k] * W[n,k] ------
// CTA tile 128x128, BK=16, 4-stage cp.async. 8 warps -> 64x32 warp tiles.
#define TM 128
#define TN 128
#define TK 16
#define KPAD 20                      // row stride in floats (conflict-free frag loads)
#define STAGE_FLOATS (2 * TM * KPAD) // A tile + B tile
#define STAGES 4
#define GEMM_SMEM (STAGES * STAGE_FLOATS * 4)

__global__ __launch_bounds__(256) void gemm_mma(
    const float* __restrict__ A,
    const float* __restrict__ W0, const float* __restrict__ W1, const float* __restrict__ W2,
    float* __restrict__ C, int K, int ldc, int n1, int n2)
{
    extern __shared__ float smf[];
    const int tid  = threadIdx.x;
    const int wid  = tid >> 5, lane = tid & 31;
    const int qm   = lane >> 2, qk = lane & 3;
    const int m0   = blockIdx.y * TM;
    const int n0   = blockIdx.x * TN;
    const int wm   = (wid >> 2) * 64;       // warp row offset
    const int wn   = (wid & 3) * 32;        // warp col offset

    const float* W; int nr;
    if (n0 < n1)      { W = W0; nr = n0; }
    else if (n0 < n2) { W = W1; nr = n0 - n1; }
    else              { W = W2; nr = n0 - n2; }

    const float* Abase = A + (size_t)m0 * K;
    const float* Wbase = W + (size_t)nr * K;
    const uint32_t sb = smem_u32(smf);

    float acc[4][4][4];
    #pragma unroll
    for (int i = 0; i < 4; ++i)
        #pragma unroll
        for (int j = 0; j < 4; ++j)
            #pragma unroll
            for (int r = 0; r < 4; ++r) acc[i][j][r] = 0.f;

    const int NCH = K / TK;   // 128 for K=2048

    auto load_chunk = [&](int c, int buf) {
        const uint32_t abuf = sb + (uint32_t)buf * STAGE_FLOATS * 4;
        const uint32_t bbuf = abuf + TM * KPAD * 4;
        const int k0 = c * TK;
        #pragma unroll
        for (int i = 0; i < 2; ++i) {
            int idx = tid + i * 256;          // 0..511 over A chunks
            int row = idx >> 2, c4 = idx & 3;
            cp_async16(abuf + (uint32_t)(row * KPAD + c4 * 4) * 4,
                       Abase + (size_t)row * K + k0 + c4 * 4);
            cp_async16(bbuf + (uint32_t)(row * KPAD + c4 * 4) * 4,
                       Wbase + (size_t)row * K + k0 + c4 * 4);
        }
        cp_commit();
    };

    #pragma unroll
    for (int s = 0; s < STAGES - 1; ++s) load_chunk(s, s);

    for (int c = 0; c < NCH; ++c) {
        cp_wait<STAGES - 2>();
        __syncthreads();

        const int cn = c + STAGES - 1;
        if (cn < NCH) load_chunk(cn, cn & (STAGES - 1));
        else          cp_commit();

        const float* As = smf + (size_t)(c & (STAGES - 1)) * STAGE_FLOATS;
        const float* Bs = As + TM * KPAD;

        #pragma unroll
        for (int ks = 0; ks < 2; ++ks) {
            const int k0 = ks * 8;
            uint32_t af[4][4], bf[4][2];
            #pragma unroll
            for (int mt = 0; mt < 4; ++mt) {
                const float* ap = As + (wm + mt * 16 + qm) * KPAD + k0 + qk;
                af[mt][0] = f2tf32(ap[0]);
                af[mt][1] = f2tf32(ap[8 * KPAD]);
                af[mt][2] = f2tf32(ap[4]);
                af[mt][3] = f2tf32(ap[8 * KPAD + 4]);
            }
            #pragma unroll
            for (int nt = 0; nt < 4; ++nt) {
                const float* bp = Bs + (wn + nt * 8 + qm) * KPAD + k0 + qk;
                bf[nt][0] = f2tf32(bp[0]);
                bf[nt][1] = f2tf32(bp[4]);
            }
            #pragma unroll
            for (int mt = 0; mt < 4; ++mt)
                #pragma unroll
                for (int nt = 0; nt < 4; ++nt)
                    mma_tf32(acc[mt][nt], af[mt], bf[nt]);
        }
        __syncthreads();
    }

    // epilogue: C-fragment layout -> global
    #pragma unroll
    for (int mt = 0; mt < 4; ++mt) {
        const int r0 = m0 + wm + mt * 16 + qm;
        #pragma unroll
        for (int nt = 0; nt < 4; ++nt) {
            const int cc = n0 + wn + nt * 8 + 2 * qk;
            *(float2*)(C + (size_t)r0 * ldc + cc)       = make_float2(acc[mt][nt][0], acc[mt][nt][1]);
            *(float2*)(C + (size_t)(r0 + 8) * ldc + cc) = make_float2(acc[mt][nt][2], acc[mt][nt][3]);
        }
    }
}

// ---------------- canon conv + RMSNorm + RoPE + relayout ---------------------
__global__ __launch_bounds__(256) void postproc_kernel(
    const float* __restrict__ qkv,
    const float* __restrict__ cwq, const float* __restrict__ cwk, const float* __restrict__ cwv,
    const float* __restrict__ qnw, const float* __restrict__ knw,
    const float2* __restrict__ rope,
    float* __restrict__ qo, float* __restrict__ ko, float* __restrict__ vo)
{
    __shared__ float sm[4096];
    const int s   = blockIdx.x;
    const int b   = blockIdx.y;
    const int tid = threadIdx.x;
    const float* row0 = qkv + ((size_t)b * S_ + s) * 4096;

    for (int c = tid; c < 4096; c += 256) {
        const float* cw;
        if (c < 2048)       cw = cwq + (size_t)c * 4;
        else if (c < 3072)  cw = cwk + (size_t)(c - 2048) * 4;
        else                cw = cwv + (size_t)(c - 3072) * 4;
        float x0  = row0[c];
        float acc = x0 + cw[0] * x0;
        if (s >= 1) acc = fmaf(cw[1], row0[c - 4096],     acc);
        if (s >= 2) acc = fmaf(cw[2], row0[c - 2 * 4096], acc);
        if (s >= 3) acc = fmaf(cw[3], row0[c - 3 * 4096], acc);
        sm[c] = acc;
    }
    __syncthreads();

    for (int idx = tid; idx < KV_ * DH_; idx += 256) {
        int kvh = idx >> 7, d = idx & 127;
        vo[(((size_t)b * KV_ + kvh) * S_ + s) * DH_ + d] = sm[3072 + idx];
    }

    const int warp = tid >> 5, lane = tid & 31;
    const float2 cs0 = rope[(size_t)s * 64 + lane];
    const float2 cs1 = rope[(size_t)s * 64 + lane + 32];
    for (int h24 = warp; h24 < 24; h24 += 8) {
        bool isq  = h24 < 16;
        int  base = isq ? h24 * 128 : 2048 + (h24 - 16) * 128;
        float v0 = sm[base + lane];
        float v1 = sm[base + lane + 32];
        float v2 = sm[base + lane + 64];
        float v3 = sm[base + lane + 96];
        float ss = v0*v0 + v1*v1 + v2*v2 + v3*v3;
        #pragma unroll
        for (int o = 16; o > 0; o >>= 1) ss += __shfl_xor_sync(0xffffffffu, ss, o);
        float r = rsqrtf(ss * (1.0f / 128.0f) + 1e-6f);
        const float* nw = isq ? qnw : knw;
        float a0 = v0 * r * nw[lane];
        float a1 = v1 * r * nw[lane + 32];
        float a2 = v2 * r * nw[lane + 64];
        float a3 = v3 * r * nw[lane + 96];
        float o_lo0 = a0 * cs0.x - a2 * cs0.y;
        float o_hi0 = a2 * cs0.x + a0 * cs0.y;
        float o_lo1 = a1 * cs1.x - a3 * cs1.y;
        float o_hi1 = a3 * cs1.x + a1 * cs1.y;
        float* dst;
        if (isq) dst = qo + (((size_t)b * H_  + h24)        * S_ + s) * DH_;
        else     dst = ko + (((size_t)b * KV_ + (h24 - 16)) * S_ + s) * DH_;
        dst[lane]      = o_lo0;
        dst[lane + 32] = o_lo1;
        dst[lane + 64] = o_hi0;
        dst[lane + 96] = o_hi1;
    }
}

// ---------------- causal flash attention (fp32), BM=BN=64 --------------------
__global__ __launch_bounds__(256) void flash_attn_kernel(
    const float* __restrict__ Q, const float* __restrict__ Kg,
    const float* __restrict__ Vg, float* __restrict__ O)
{
    extern __shared__ float fsm[];
    float* Qs = fsm;
    float* Ks = Qs + 128 * 65;
    float* Vs = Ks + 128 * 65;
    float* Ps = Vs + 64 * 128;

    const int q0  = blockIdx.x * 64;
    const int h   = blockIdx.y;
    const int b   = blockIdx.z;
    const int tid = threadIdx.x;
    const int ty  = tid >> 4, tx = tid & 15;
    const int trow = ty * 4;
    const float scale = 0.08838834764831845f;

    const float* Qbase = Q  + (((size_t)b * H_  + h)        * S_ + q0) * DH_;
    const float* Kbase = Kg + (((size_t)b * KV_ + (h >> 1)) * S_)      * DH_;
    const float* Vbase = Vg + (((size_t)b * KV_ + (h >> 1)) * S_)      * DH_;

    for (int idx = tid; idx < 64 * 32; idx += 256) {
        int r = idx >> 5, c4 = idx & 31;
        float4 v = *(const float4*)(Qbase + (size_t)r * 128 + c4 * 4);
        Qs[(c4 * 4 + 0) * 65 + r] = v.x;
        Qs[(c4 * 4 + 1) * 65 + r] = v.y;
        Qs[(c4 * 4 + 2) * 65 + r] = v.z;
        Qs[(c4 * 4 + 3) * 65 + r] = v.w;
    }

    float acc[4][8];
    float m_i[4], l_i[4];
    #pragma unroll
    for (int i = 0; i < 4; ++i) {
        m_i[i] = -1e30f; l_i[i] = 0.f;
        #pragma unroll
        for (int c = 0; c < 8; ++c) acc[i][c] = 0.f;
    }

    const int nblocks = (q0 >> 6) + 1;
    for (int jb = 0; jb < nblocks; ++jb) {
        const int j0 = jb * 64;
        __syncthreads();
        for (int idx = tid; idx < 64 * 32; idx += 256) {
            int r = idx >> 5, c4 = idx & 31;
            float4 v = *(const float4*)(Kbase + (size_t)(j0 + r) * 128 + c4 * 4);
            Ks[(c4 * 4 + 0) * 65 + r] = v.x;
            Ks[(c4 * 4 + 1) * 65 + r] = v.y;
            Ks[(c4 * 4 + 2) * 65 + r] = v.z;
            Ks[(c4 * 4 + 3) * 65 + r] = v.w;
            float4 w = *(const float4*)(Vbase + (size_t)(j0 + r) * 128 + c4 * 4);
            *(float4*)(Vs + r * 128 + c4 * 4) = w;
        }
        __syncthreads();

        float sv[4][4];
        #pragma unroll
        for (int i = 0; i < 4; ++i)
            #pragma unroll
            for (int j = 0; j < 4; ++j) sv[i][j] = 0.f;
        #pragma unroll 4
        for (int k = 0; k < 128; ++k) {
            float af[4], bf[4];
            #pragma unroll
            for (int i = 0; i < 4; ++i) af[i] = Qs[k * 65 + trow + i];
            #pragma unroll
            for (int j = 0; j < 4; ++j) bf[j] = Ks[k * 65 + tx * 4 + j];
            #pragma unroll
            for (int i = 0; i < 4; ++i)
                #pragma unroll
                for (int j = 0; j < 4; ++j)
                    sv[i][j] = fmaf(af[i], bf[j], sv[i][j]);
        }

        const bool diag = (jb == nblocks - 1);
        #pragma unroll
        for (int i = 0; i < 4; ++i) {
            const int qrow = q0 + trow + i;
            #pragma unroll
            for (int j = 0; j < 4; ++j) {
                float x = sv[i][j] * scale;
                if (diag && (j0 + tx * 4 + j > qrow)) x = -1e30f;
                sv[i][j] = x;
            }
        }

        #pragma unroll
        for (int i = 0; i < 4; ++i) {
            float mx = fmaxf(fmaxf(sv[i][0], sv[i][1]), fmaxf(sv[i][2], sv[i][3]));
            #pragma unroll
            for (int o = 8; o > 0; o >>= 1) mx = fmaxf(mx, __shfl_xor_sync(0xffffffffu, mx, o));
            float mnew  = fmaxf(m_i[i], mx);
            float alpha = __expf(m_i[i] - mnew);
            float rs = 0.f;
            #pragma unroll
            for (int j = 0; j < 4; ++j) {
                float p = __expf(sv[i][j] - mnew);
                sv[i][j] = p;
                rs += p;
            }
            #pragma unroll
            for (int o = 8; o > 0; o >>= 1) rs += __shfl_xor_sync(0xffffffffu, rs, o);
            l_i[i] = l_i[i] * alpha + rs;
            m_i[i] = mnew;
            #pragma unroll
            for (int c = 0; c < 8; ++c) acc[i][c] *= alpha;
            #pragma unroll
            for (int j = 0; j < 4; ++j) Ps[(tx * 4 + j) * 65 + trow + i] = sv[i][j];
        }
        __syncthreads();

        #pragma unroll 2
        for (int j = 0; j < 64; ++j) {
            float pf[4];
            #pragma unroll
            for (int i = 0; i < 4; ++i) pf[i] = Ps[j * 65 + trow + i];
            float4 vlo = *(const float4*)(Vs + j * 128 + tx * 8);
            float4 vhi = *(const float4*)(Vs + j * 128 + tx * 8 + 4);
            float vf[8] = {vlo.x, vlo.y, vlo.z, vlo.w, vhi.x, vhi.y, vhi.z, vhi.w};
            #pragma unroll
            for (int i = 0; i < 4; ++i)
                #pragma unroll
                for (int c = 0; c < 8; ++c)
                    acc[i][c] = fmaf(pf[i], vf[c], acc[i][c]);
        }
    }

    #pragma unroll
    for (int i = 0; i < 4; ++i) {
        float inv = 1.f / l_i[i];
        float* orow = O + ((size_t)b * S_ + q0 + trow + i) * D_ + h * DH_ + tx * 8;
        #pragma unroll
        for (int c = 0; c < 8; ++c) orow[c] = acc[i][c] * inv;
    }
}

// ---------------- launch ----------------
extern "C" void kernel_launch(void* const* d_in, const int* in_sizes, int n_in,
                              void* d_out, int out_size)
{
    const float* hidden = (const float*)d_in[0];
    const float* Wq     = (const float*)d_in[1];
    const float* Wk     = (const float*)d_in[2];
    const float* Wv     = (const float*)d_in[3];
    const float* Wo     = (const float*)d_in[4];
    const float* cwq    = (const float*)d_in[5];
    const float* cwk    = (const float*)d_in[6];
    const float* cwv    = (const float*)d_in[7];
    const float* qnw    = (const float*)d_in[8];
    const float* knw    = (const float*)d_in[9];
    float* out = (float*)d_out;

    float  *qkv, *q, *k, *v, *attn;
    float2 *rope;
    cudaGetSymbolAddress((void**)&qkv,  g_qkv);
    cudaGetSymbolAddress((void**)&q,    g_q);
    cudaGetSymbolAddress((void**)&k,    g_k);
    cudaGetSymbolAddress((void**)&v,    g_v);
    cudaGetSymbolAddress((void**)&attn, g_attn);
    cudaGetSymbolAddress((void**)&rope, g_rope);

    rope_init_kernel<<<(S_ * 64 + 255) / 256, 256>>>(rope);

    cudaFuncSetAttribute(gemm_mma, cudaFuncAttributeMaxDynamicSharedMemorySize, GEMM_SMEM);

    // fused QKV projection: N = 4096 (q | k | v)
    gemm_mma<<<dim3(4096 / TN, (B_ * S_) / TM), 256, GEMM_SMEM>>>(
        hidden, Wq, Wk, Wv, qkv, 2048, 4096, 2048, 3072);

    postproc_kernel<<<dim3(S_, B_), 256>>>(qkv, cwq, cwk, cwv, qnw, knw, rope, q, k, v);

    size_t shmem = (size_t)(128 * 65 + 128 * 65 + 64 * 128 + 64 * 65) * sizeof(float);
    cudaFuncSetAttribute(flash_attn_kernel,
                         cudaFuncAttributeMaxDynamicSharedMemorySize, (int)shmem);
    flash_attn_kernel<<<dim3(S_ / 64, H_, B_), 256, shmem>>>(q, k, v, attn);

    // output projection
    gemm_mma<<<dim3(D_ / TN, (B_ * S_) / TM), 256, GEMM_SMEM>>>(
        attn, Wo, Wo, Wo, out, 2048, 2048, 1 << 30, 1 << 30);
}

// round 4
// speedup vs baseline: 3.2144x; 1.9489x over previous
#include <cuda_runtime.h>
#include <math.h>
#include <stdint.h>

#define B_   2
#define S_   2048
#define D_   2048
#define H_   16
#define KV_  8
#define DH_  128

// ---------------- persistent scratch ----------------
__device__ float  g_qkv [B_ * S_ * 4096];        // q|k|v concatenated, [B*S, 4096]
__device__ float  g_q   [B_ * H_  * S_ * DH_];
__device__ float  g_k   [B_ * KV_ * S_ * DH_];
__device__ float  g_v   [B_ * KV_ * S_ * DH_];
__device__ float  g_attn[B_ * S_ * D_];
__device__ float2 g_rope[S_ * 64];

// ---------------- PTX helpers (sm_80-era; tcgen05 not available via compute_103) ----
__device__ __forceinline__ uint32_t smem_u32(const void* p) {
    uint32_t a;
    asm("{ .reg .u64 t; cvta.to.shared.u64 t, %1; cvt.u32.u64 %0, t; }" : "=r"(a) : "l"(p));
    return a;
}
__device__ __forceinline__ void cp_async16(uint32_t saddr, const void* gaddr) {
    asm volatile("cp.async.cg.shared.global [%0], [%1], 16;" :: "r"(saddr), "l"(gaddr));
}
__device__ __forceinline__ void cp_commit() {
    asm volatile("cp.async.commit_group;" ::: "memory");
}
template <int N>
__device__ __forceinline__ void cp_wait() {
    asm volatile("cp.async.wait_group %0;" :: "n"(N) : "memory");
}
__device__ __forceinline__ uint32_t f2tf32(float x) {
    uint32_t r;
    asm("cvt.rna.tf32.f32 %0, %1;" : "=r"(r) : "f"(x));
    return r;
}
__device__ __forceinline__ void mma_tf32(float* c, const uint32_t* a, const uint32_t* b) {
    asm volatile(
        "mma.sync.aligned.m16n8k8.row.col.f32.tf32.tf32.f32 "
        "{%0,%1,%2,%3}, {%4,%5,%6,%7}, {%8,%9}, {%0,%1,%2,%3};"
        : "+f"(c[0]), "+f"(c[1]), "+f"(c[2]), "+f"(c[3])
        : "r"(a[0]), "r"(a[1]), "r"(a[2]), "r"(a[3]), "r"(b[0]), "r"(b[1]));
}

// ---------------- RoPE table ----------------
__global__ void rope_init_kernel(float2* __restrict__ tab) {
    int idx = blockIdx.x * blockDim.x + threadIdx.x;
    if (idx >= S_ * 64) return;
    int s = idx >> 6, j = idx & 63;
    double inv = exp(-(double)j * (9.210340371976184 / 64.0));
    double ang = (double)s * inv;
    tab[idx] = make_float2((float)cos(ang), (float)sin(ang));
}

// ---------------- mma.sync tf32 GEMM:  C[m, n] = sum_k A[m,k] * W[n,k] ------
#define TM 128
#define TN 128
#define TK 16
#define KPAD 20
#define STAGE_FLOATS (2 * TM * KPAD)
#define STAGES 4
#define GEMM_SMEM (STAGES * STAGE_FLOATS * 4)

__global__ __launch_bounds__(256) void gemm_mma(
    const float* __restrict__ A,
    const float* __restrict__ W0, const float* __restrict__ W1, const float* __restrict__ W2,
    float* __restrict__ C, int K, int ldc, int n1, int n2)
{
    extern __shared__ float smf[];
    const int tid  = threadIdx.x;
    const int wid  = tid >> 5, lane = tid & 31;
    const int qm   = lane >> 2, qk = lane & 3;
    const int m0   = blockIdx.y * TM;
    const int n0   = blockIdx.x * TN;
    const int wm   = (wid >> 2) * 64;
    const int wn   = (wid & 3) * 32;

    const float* W; int nr;
    if (n0 < n1)      { W = W0; nr = n0; }
    else if (n0 < n2) { W = W1; nr = n0 - n1; }
    else              { W = W2; nr = n0 - n2; }

    const float* Abase = A + (size_t)m0 * K;
    const float* Wbase = W + (size_t)nr * K;
    const uint32_t sb = smem_u32(smf);

    float acc[4][4][4];
    #pragma unroll
    for (int i = 0; i < 4; ++i)
        #pragma unroll
        for (int j = 0; j < 4; ++j)
            #pragma unroll
            for (int r = 0; r < 4; ++r) acc[i][j][r] = 0.f;

    const int NCH = K / TK;

    auto load_chunk = [&](int c, int buf) {
        const uint32_t abuf = sb + (uint32_t)buf * STAGE_FLOATS * 4;
        const uint32_t bbuf = abuf + TM * KPAD * 4;
        const int k0 = c * TK;
        #pragma unroll
        for (int i = 0; i < 2; ++i) {
            int idx = tid + i * 256;
            int row = idx >> 2, c4 = idx & 3;
            cp_async16(abuf + (uint32_t)(row * KPAD + c4 * 4) * 4,
                       Abase + (size_t)row * K + k0 + c4 * 4);
            cp_async16(bbuf + (uint32_t)(row * KPAD + c4 * 4) * 4,
                       Wbase + (size_t)row * K + k0 + c4 * 4);
        }
        cp_commit();
    };

    #pragma unroll
    for (int s = 0; s < STAGES - 1; ++s) load_chunk(s, s);

    for (int c = 0; c < NCH; ++c) {
        cp_wait<STAGES - 2>();
        __syncthreads();

        const int cn = c + STAGES - 1;
        if (cn < NCH) load_chunk(cn, cn & (STAGES - 1));
        else          cp_commit();

        const float* As = smf + (size_t)(c & (STAGES - 1)) * STAGE_FLOATS;
        const float* Bs = As + TM * KPAD;

        #pragma unroll
        for (int ks = 0; ks < 2; ++ks) {
            const int k0 = ks * 8;
            uint32_t af[4][4], bf[4][2];
            #pragma unroll
            for (int mt = 0; mt < 4; ++mt) {
                const float* ap = As + (wm + mt * 16 + qm) * KPAD + k0 + qk;
                af[mt][0] = f2tf32(ap[0]);
                af[mt][1] = f2tf32(ap[8 * KPAD]);
                af[mt][2] = f2tf32(ap[4]);
                af[mt][3] = f2tf32(ap[8 * KPAD + 4]);
            }
            #pragma unroll
            for (int nt = 0; nt < 4; ++nt) {
                const float* bp = Bs + (wn + nt * 8 + qm) * KPAD + k0 + qk;
                bf[nt][0] = f2tf32(bp[0]);
                bf[nt][1] = f2tf32(bp[4]);
            }
            #pragma unroll
            for (int mt = 0; mt < 4; ++mt)
                #pragma unroll
                for (int nt = 0; nt < 4; ++nt)
                    mma_tf32(acc[mt][nt], af[mt], bf[nt]);
        }
        __syncthreads();
    }

    #pragma unroll
    for (int mt = 0; mt < 4; ++mt) {
        const int r0 = m0 + wm + mt * 16 + qm;
        #pragma unroll
        for (int nt = 0; nt < 4; ++nt) {
            const int cc = n0 + wn + nt * 8 + 2 * qk;
            *(float2*)(C + (size_t)r0 * ldc + cc)       = make_float2(acc[mt][nt][0], acc[mt][nt][1]);
            *(float2*)(C + (size_t)(r0 + 8) * ldc + cc) = make_float2(acc[mt][nt][2], acc[mt][nt][3]);
        }
    }
}

// ---------------- canon conv + RMSNorm + RoPE + relayout (tf32 pre-round) ----
__global__ __launch_bounds__(256) void postproc_kernel(
    const float* __restrict__ qkv,
    const float* __restrict__ cwq, const float* __restrict__ cwk, const float* __restrict__ cwv,
    const float* __restrict__ qnw, const float* __restrict__ knw,
    const float2* __restrict__ rope,
    float* __restrict__ qo, float* __restrict__ ko, float* __restrict__ vo)
{
    __shared__ float sm[4096];
    const int s   = blockIdx.x;
    const int b   = blockIdx.y;
    const int tid = threadIdx.x;
    const float* row0 = qkv + ((size_t)b * S_ + s) * 4096;
    const float sc = 0.08838834764831845f;   // 1/sqrt(128), folded into Q

    for (int c = tid; c < 4096; c += 256) {
        const float* cw;
        if (c < 2048)       cw = cwq + (size_t)c * 4;
        else if (c < 3072)  cw = cwk + (size_t)(c - 2048) * 4;
        else                cw = cwv + (size_t)(c - 3072) * 4;
        float x0  = row0[c];
        float acc = x0 + cw[0] * x0;
        if (s >= 1) acc = fmaf(cw[1], row0[c - 4096],     acc);
        if (s >= 2) acc = fmaf(cw[2], row0[c - 2 * 4096], acc);
        if (s >= 3) acc = fmaf(cw[3], row0[c - 3 * 4096], acc);
        sm[c] = acc;
    }
    __syncthreads();

    // V: tf32 pre-rounded copy
    for (int idx = tid; idx < KV_ * DH_; idx += 256) {
        int kvh = idx >> 7, d = idx & 127;
        vo[(((size_t)b * KV_ + kvh) * S_ + s) * DH_ + d] =
            __uint_as_float(f2tf32(sm[3072 + idx]));
    }

    const int warp = tid >> 5, lane = tid & 31;
    const float2 cs0 = rope[(size_t)s * 64 + lane];
    const float2 cs1 = rope[(size_t)s * 64 + lane + 32];
    for (int h24 = warp; h24 < 24; h24 += 8) {
        bool isq  = h24 < 16;
        int  base = isq ? h24 * 128 : 2048 + (h24 - 16) * 128;
        float v0 = sm[base + lane];
        float v1 = sm[base + lane + 32];
        float v2 = sm[base + lane + 64];
        float v3 = sm[base + lane + 96];
        float ss = v0*v0 + v1*v1 + v2*v2 + v3*v3;
        #pragma unroll
        for (int o = 16; o > 0; o >>= 1) ss += __shfl_xor_sync(0xffffffffu, ss, o);
        float r = rsqrtf(ss * (1.0f / 128.0f) + 1e-6f);
        const float* nw = isq ? qnw : knw;
        float a0 = v0 * r * nw[lane];
        float a1 = v1 * r * nw[lane + 32];
        float a2 = v2 * r * nw[lane + 64];
        float a3 = v3 * r * nw[lane + 96];
        float o_lo0 = a0 * cs0.x - a2 * cs0.y;
        float o_hi0 = a2 * cs0.x + a0 * cs0.y;
        float o_lo1 = a1 * cs1.x - a3 * cs1.y;
        float o_hi1 = a3 * cs1.x + a1 * cs1.y;
        float* dst;
        float f = 1.0f;
        if (isq) { dst = qo + (((size_t)b * H_  + h24)        * S_ + s) * DH_; f = sc; }
        else     { dst = ko + (((size_t)b * KV_ + (h24 - 16)) * S_ + s) * DH_; }
        dst[lane]      = __uint_as_float(f2tf32(o_lo0 * f));
        dst[lane + 32] = __uint_as_float(f2tf32(o_lo1 * f));
        dst[lane + 64] = __uint_as_float(f2tf32(o_hi0 * f));
        dst[lane + 96] = __uint_as_float(f2tf32(o_hi1 * f));
    }
}

// ---------------- causal flash attention, tf32 mma.sync ----------------------
// BM=128 (8 warps x 16 rows), BN=64, D=128. K/V double-buffered cp.async.
#define FA_KS 132
#define FA_VS 136
#define FA_PS 68
#define FA_KTILE (64 * FA_KS)
#define FA_VTILE (64 * FA_VS)
#define FA_SMEM ((2 * FA_KTILE + 2 * FA_VTILE + 128 * FA_PS) * 4)

__global__ __launch_bounds__(256) void flash_mma_kernel(
    const float* __restrict__ Q, const float* __restrict__ Kg,
    const float* __restrict__ Vg, float* __restrict__ O)
{
    extern __shared__ float fs[];
    float* Ks0 = fs;
    float* Vs0 = fs + 2 * FA_KTILE;
    float* Ps  = fs + 2 * FA_KTILE + 2 * FA_VTILE;

    const int qblk = gridDim.x - 1 - blockIdx.x;   // big blocks first
    const int q0   = qblk * 128;
    const int h    = blockIdx.y;
    const int b    = blockIdx.z;
    const int tid  = threadIdx.x;
    const int w    = tid >> 5, lane = tid & 31;
    const int qm   = lane >> 2, qk = lane & 3;
    const int wrow = w * 16;

    const float* Qb = Q  + (((size_t)b * H_  + h)        * S_ + q0 + wrow) * DH_;
    const float* Kb = Kg + (((size_t)b * KV_ + (h >> 1)) * S_) * DH_;
    const float* Vb = Vg + (((size_t)b * KV_ + (h >> 1)) * S_) * DH_;

    // Q fragments (pre-scaled + tf32-rounded by postproc)
    uint32_t qf[16][4];
    #pragma unroll
    for (int ks = 0; ks < 16; ++ks) {
        qf[ks][0] = __float_as_uint(Qb[(size_t)qm * DH_ + ks * 8 + qk]);
        qf[ks][1] = __float_as_uint(Qb[(size_t)(qm + 8) * DH_ + ks * 8 + qk]);
        qf[ks][2] = __float_as_uint(Qb[(size_t)qm * DH_ + ks * 8 + qk + 4]);
        qf[ks][3] = __float_as_uint(Qb[(size_t)(qm + 8) * DH_ + ks * 8 + qk + 4]);
    }

    float o[16][4];
    #pragma unroll
    for (int nt = 0; nt < 16; ++nt)
        o[nt][0] = o[nt][1] = o[nt][2] = o[nt][3] = 0.f;
    float m0v = -1e30f, m1v = -1e30f, l0 = 0.f, l1 = 0.f;

    const int nb = 2 * (qblk + 1);
    const uint32_t ks_u = smem_u32(Ks0);
    const uint32_t vs_u = smem_u32(Vs0);

    auto prefetch = [&](int jb, int buf) {
        const int j0 = jb * 64;
        #pragma unroll
        for (int i = 0; i < 8; ++i) {
            int idx = tid + i * 256;
            int row = idx >> 5, c4 = idx & 31;
            cp_async16(ks_u + (uint32_t)(buf * FA_KTILE + row * FA_KS + c4 * 4) * 4,
                       Kb + (size_t)(j0 + row) * DH_ + c4 * 4);
            cp_async16(vs_u + (uint32_t)(buf * FA_VTILE + row * FA_VS + c4 * 4) * 4,
                       Vb + (size_t)(j0 + row) * DH_ + c4 * 4);
        }
        cp_commit();
    };

    prefetch(0, 0);

    for (int jb = 0; jb < nb; ++jb) {
        const int buf = jb & 1;
        const int j0  = jb * 64;

        __syncthreads();                       // all warps done reading buf^1
        if (jb + 1 < nb) prefetch(jb + 1, buf ^ 1);
        else             cp_commit();
        cp_wait<1>();                          // tile jb resident
        __syncthreads();

        const float* Kt = Ks0 + buf * FA_KTILE;
        const float* Vt = Vs0 + buf * FA_VTILE;

        // ---- S = Q K^T ----
        float sv[8][4];
        #pragma unroll
        for (int nt = 0; nt < 8; ++nt) {
            sv[nt][0] = sv[nt][1] = sv[nt][2] = sv[nt][3] = 0.f;
            const float* kp = Kt + (nt * 8 + qm) * FA_KS + qk;
            #pragma unroll
            for (int ks = 0; ks < 16; ++ks) {
                uint32_t bfr[2];
                bfr[0] = __float_as_uint(kp[ks * 8]);
                bfr[1] = __float_as_uint(kp[ks * 8 + 4]);
                mma_tf32(sv[nt], qf[ks], bfr);
            }
        }

        // ---- causal mask (last two tiles only) ----
        if (jb >= nb - 2) {
            const int r0 = q0 + wrow + qm, r1 = r0 + 8;
            #pragma unroll
            for (int nt = 0; nt < 8; ++nt) {
                const int c0 = j0 + nt * 8 + 2 * qk;
                if (c0     > r0) sv[nt][0] = -1e30f;
                if (c0 + 1 > r0) sv[nt][1] = -1e30f;
                if (c0     > r1) sv[nt][2] = -1e30f;
                if (c0 + 1 > r1) sv[nt][3] = -1e30f;
            }
        }

        // ---- online softmax ----
        float mx0 = -1e30f, mx1 = -1e30f;
        #pragma unroll
        for (int nt = 0; nt < 8; ++nt) {
            mx0 = fmaxf(mx0, fmaxf(sv[nt][0], sv[nt][1]));
            mx1 = fmaxf(mx1, fmaxf(sv[nt][2], sv[nt][3]));
        }
        mx0 = fmaxf(mx0, __shfl_xor_sync(0xffffffffu, mx0, 1));
        mx0 = fmaxf(mx0, __shfl_xor_sync(0xffffffffu, mx0, 2));
        mx1 = fmaxf(mx1, __shfl_xor_sync(0xffffffffu, mx1, 1));
        mx1 = fmaxf(mx1, __shfl_xor_sync(0xffffffffu, mx1, 2));

        const float mn0 = fmaxf(m0v, mx0), mn1 = fmaxf(m1v, mx1);
        const float a0 = __expf(m0v - mn0), a1 = __expf(m1v - mn1);
        float rs0 = 0.f, rs1 = 0.f;

        float* prow0 = Ps + (wrow + qm) * FA_PS + 2 * qk;
        float* prow1 = prow0 + 8 * FA_PS;
        #pragma unroll
        for (int nt = 0; nt < 8; ++nt) {
            float p00 = __expf(sv[nt][0] - mn0);
            float p01 = __expf(sv[nt][1] - mn0);
            float p10 = __expf(sv[nt][2] - mn1);
            float p11 = __expf(sv[nt][3] - mn1);
            rs0 += p00 + p01;
            rs1 += p10 + p11;
            *(float2*)(prow0 + nt * 8) =
                make_float2(__uint_as_float(f2tf32(p00)), __uint_as_float(f2tf32(p01)));
            *(float2*)(prow1 + nt * 8) =
                make_float2(__uint_as_float(f2tf32(p10)), __uint_as_float(f2tf32(p11)));
        }
        rs0 += __shfl_xor_sync(0xffffffffu, rs0, 1);
        rs0 += __shfl_xor_sync(0xffffffffu, rs0, 2);
        rs1 += __shfl_xor_sync(0xffffffffu, rs1, 1);
        rs1 += __shfl_xor_sync(0xffffffffu, rs1, 2);

        l0 = l0 * a0 + rs0;  l1 = l1 * a1 + rs1;
        m0v = mn0;           m1v = mn1;
        #pragma unroll
        for (int nt = 0; nt < 16; ++nt) {
            o[nt][0] *= a0; o[nt][1] *= a0;
            o[nt][2] *= a1; o[nt][3] *= a1;
        }

        __syncthreads();   // P tile visible to all warps

        // ---- O += P V ----
        uint32_t aP[8][4];
        const float* pp = Ps + (wrow + qm) * FA_PS + qk;
        #pragma unroll
        for (int ks = 0; ks < 8; ++ks) {
            aP[ks][0] = __float_as_uint(pp[ks * 8]);
            aP[ks][1] = __float_as_uint(pp[8 * FA_PS + ks * 8]);
            aP[ks][2] = __float_as_uint(pp[ks * 8 + 4]);
            aP[ks][3] = __float_as_uint(pp[8 * FA_PS + ks * 8 + 4]);
        }
        #pragma unroll
        for (int nt = 0; nt < 16; ++nt) {
            const float* vp = Vt + qk * FA_VS + nt * 8 + qm;
            #pragma unroll
            for (int ks = 0; ks < 8; ++ks) {
                uint32_t bfr[2];
                bfr[0] = __float_as_uint(vp[(ks * 8)     * FA_VS]);
                bfr[1] = __float_as_uint(vp[(ks * 8 + 4) * FA_VS]);
                mma_tf32(o[nt], aP[ks], bfr);
            }
        }
    }

    // ---- epilogue ----
    const float il0 = 1.f / l0, il1 = 1.f / l1;
    const int row0 = q0 + wrow + qm, row1 = row0 + 8;
    float* O0 = O + ((size_t)b * S_ + row0) * D_ + h * DH_ + 2 * qk;
    float* O1 = O + ((size_t)b * S_ + row1) * D_ + h * DH_ + 2 * qk;
    #pragma unroll
    for (int nt = 0; nt < 16; ++nt) {
        *(float2*)(O0 + nt * 8) = make_float2(o[nt][0] * il0, o[nt][1] * il0);
        *(float2*)(O1 + nt * 8) = make_float2(o[nt][2] * il1, o[nt][3] * il1);
    }
}

// ---------------- launch ----------------
extern "C" void kernel_launch(void* const* d_in, const int* in_sizes, int n_in,
                              void* d_out, int out_size)
{
    const float* hidden = (const float*)d_in[0];
    const float* Wq     = (const float*)d_in[1];
    const float* Wk     = (const float*)d_in[2];
    const float* Wv     = (const float*)d_in[3];
    const float* Wo     = (const float*)d_in[4];
    const float* cwq    = (const float*)d_in[5];
    const float* cwk    = (const float*)d_in[6];
    const float* cwv    = (const float*)d_in[7];
    const float* qnw    = (const float*)d_in[8];
    const float* knw    = (const float*)d_in[9];
    float* out = (float*)d_out;

    float  *qkv, *q, *k, *v, *attn;
    float2 *rope;
    cudaGetSymbolAddress((void**)&qkv,  g_qkv);
    cudaGetSymbolAddress((void**)&q,    g_q);
    cudaGetSymbolAddress((void**)&k,    g_k);
    cudaGetSymbolAddress((void**)&v,    g_v);
    cudaGetSymbolAddress((void**)&attn, g_attn);
    cudaGetSymbolAddress((void**)&rope, g_rope);

    rope_init_kernel<<<(S_ * 64 + 255) / 256, 256>>>(rope);

    cudaFuncSetAttribute(gemm_mma, cudaFuncAttributeMaxDynamicSharedMemorySize, GEMM_SMEM);

    // fused QKV projection: N = 4096 (q | k | v)
    gemm_mma<<<dim3(4096 / TN, (B_ * S_) / TM), 256, GEMM_SMEM>>>(
        hidden, Wq, Wk, Wv, qkv, 2048, 4096, 2048, 3072);

    postproc_kernel<<<dim3(S_, B_), 256>>>(qkv, cwq, cwk, cwv, qnw, knw, rope, q, k, v);

    cudaFuncSetAttribute(flash_mma_kernel, cudaFuncAttributeMaxDynamicSharedMemorySize, FA_SMEM);
    flash_mma_kernel<<<dim3(S_ / 128, H_, B_), 256, FA_SMEM>>>(q, k, v, attn);

    // output projection
    gemm_mma<<<dim3(D_ / TN, (B_ * S_) / TM), 256, GEMM_SMEM>>>(
        attn, Wo, Wo, Wo, out, 2048, 2048, 1 << 30, 1 << 30);
}

// round 5
// speedup vs baseline: 3.7865x; 1.1780x over previous
#include <cuda_runtime.h>
#include <math.h>
#include <stdint.h>

#define B_   2
#define S_   2048
#define D_   2048
#define H_   16
#define KV_  8
#define DH_  128

// ---------------- persistent scratch ----------------
__device__ float  g_qkv [B_ * S_ * 4096];        // q|k|v concatenated
__device__ float  g_q   [B_ * H_  * S_ * DH_];   // k-permuted, tf32
__device__ float  g_k   [B_ * KV_ * S_ * DH_];   // k-permuted, tf32
__device__ float  g_v   [B_ * KV_ * S_ * DH_];   // tf32
__device__ float  g_attn[B_ * S_ * D_];          // k-permuted, tf32
__device__ float2 g_rope[S_ * 64];
// tf32-rounded + k-permuted operand copies
__device__ float  g_hid [B_ * S_ * D_];
__device__ float  g_wq  [D_ * D_];
__device__ float  g_wk  [1024 * D_];
__device__ float  g_wv  [1024 * D_];
__device__ float  g_wo  [D_ * D_];

// ---------------- PTX helpers ----------------
__device__ __forceinline__ uint32_t smem_u32(const void* p) {
    uint32_t a;
    asm("{ .reg .u64 t; cvta.to.shared.u64 t, %1; cvt.u32.u64 %0, t; }" : "=r"(a) : "l"(p));
    return a;
}
__device__ __forceinline__ void cp_async16(uint32_t saddr, const void* gaddr) {
    asm volatile("cp.async.cg.shared.global [%0], [%1], 16;" :: "r"(saddr), "l"(gaddr));
}
__device__ __forceinline__ void cp_commit() {
    asm volatile("cp.async.commit_group;" ::: "memory");
}
template <int N>
__device__ __forceinline__ void cp_wait() {
    asm volatile("cp.async.wait_group %0;" :: "n"(N) : "memory");
}
__device__ __forceinline__ uint32_t f2tf32(float x) {
    uint32_t r;
    asm("cvt.rna.tf32.f32 %0, %1;" : "=r"(r) : "f"(x));
    return r;
}
__device__ __forceinline__ float rtf(float x) { return __uint_as_float(f2tf32(x)); }
__device__ __forceinline__ void mma_tf32(float* c, const uint32_t* a, const uint32_t* b) {
    asm volatile(
        "mma.sync.aligned.m16n8k8.row.col.f32.tf32.tf32.f32 "
        "{%0,%1,%2,%3}, {%4,%5,%6,%7}, {%8,%9}, {%0,%1,%2,%3};"
        : "+f"(c[0]), "+f"(c[1]), "+f"(c[2]), "+f"(c[3])
        : "r"(a[0]), "r"(a[1]), "r"(a[2]), "r"(a[3]), "r"(b[0]), "r"(b[1]));
}

// ---------------- prepass: tf32 round + k-permute [0,4,1,5,2,6,3,7] ---------
__global__ __launch_bounds__(256) void permute_round_kernel(
    const float* __restrict__ in, float* __restrict__ out, int ngroups)
{
    int g = blockIdx.x * blockDim.x + threadIdx.x;
    if (g >= ngroups) return;
    float4 a = ((const float4*)in)[2 * g];
    float4 b = ((const float4*)in)[2 * g + 1];
    float4 o0 = make_float4(rtf(a.x), rtf(b.x), rtf(a.y), rtf(b.y));
    float4 o1 = make_float4(rtf(a.z), rtf(b.z), rtf(a.w), rtf(b.w));
    ((float4*)out)[2 * g]     = o0;
    ((float4*)out)[2 * g + 1] = o1;
}

// ---------------- RoPE table ----------------
__global__ void rope_init_kernel(float2* __restrict__ tab) {
    int idx = blockIdx.x * blockDim.x + threadIdx.x;
    if (idx >= S_ * 64) return;
    int s = idx >> 6, j = idx & 63;
    double inv = exp(-(double)j * (9.210340371976184 / 64.0));
    double ang = (double)s * inv;
    tab[idx] = make_float2((float)cos(ang), (float)sin(ang));
}

// ---------------- mma.sync tf32 GEMM (k-permuted, pre-rounded inputs) --------
#define TM 128
#define TN 128
#define TK 16
#define KPAD 24
#define STAGE_FLOATS (2 * TM * KPAD)
#define STAGES 4
#define GEMM_SMEM (STAGES * STAGE_FLOATS * 4)

__global__ __launch_bounds__(256) void gemm_mma(
    const float* __restrict__ A,
    const float* __restrict__ W0, const float* __restrict__ W1, const float* __restrict__ W2,
    float* __restrict__ C, int K, int ldc, int n1, int n2)
{
    extern __shared__ float smf[];
    const int tid  = threadIdx.x;
    const int wid  = tid >> 5, lane = tid & 31;
    const int qm   = lane >> 2, qk = lane & 3;
    const int m0   = blockIdx.y * TM;
    const int n0   = blockIdx.x * TN;
    const int wm   = (wid >> 2) * 64;
    const int wn   = (wid & 3) * 32;

    const float* W; int nr;
    if (n0 < n1)      { W = W0; nr = n0; }
    else if (n0 < n2) { W = W1; nr = n0 - n1; }
    else              { W = W2; nr = n0 - n2; }

    const float* Abase = A + (size_t)m0 * K;
    const float* Wbase = W + (size_t)nr * K;
    const uint32_t sb = smem_u32(smf);

    float acc[4][4][4];
    #pragma unroll
    for (int i = 0; i < 4; ++i)
        #pragma unroll
        for (int j = 0; j < 4; ++j)
            #pragma unroll
            for (int r = 0; r < 4; ++r) acc[i][j][r] = 0.f;

    const int NCH = K / TK;

    auto load_chunk = [&](int c, int buf) {
        const uint32_t abuf = sb + (uint32_t)buf * STAGE_FLOATS * 4;
        const uint32_t bbuf = abuf + TM * KPAD * 4;
        const int k0 = c * TK;
        #pragma unroll
        for (int i = 0; i < 2; ++i) {
            int idx = tid + i * 256;
            int row = idx >> 2, c4 = idx & 3;
            cp_async16(abuf + (uint32_t)(row * KPAD + c4 * 4) * 4,
                       Abase + (size_t)row * K + k0 + c4 * 4);
            cp_async16(bbuf + (uint32_t)(row * KPAD + c4 * 4) * 4,
                       Wbase + (size_t)row * K + k0 + c4 * 4);
        }
        cp_commit();
    };

    #pragma unroll
    for (int s = 0; s < STAGES - 1; ++s) load_chunk(s, s);

    for (int c = 0; c < NCH; ++c) {
        cp_wait<STAGES - 2>();
        __syncthreads();

        const int cn = c + STAGES - 1;
        if (cn < NCH) load_chunk(cn, cn & (STAGES - 1));
        else          cp_commit();

        const float* As = smf + (size_t)(c & (STAGES - 1)) * STAGE_FLOATS;
        const float* Bs = As + TM * KPAD;

        #pragma unroll
        for (int ks = 0; ks < 2; ++ks) {
            const int kc = ks * 8 + 2 * qk;      // permuted pair (qk, qk+4)
            uint32_t af[4][4], bf[4][2];
            #pragma unroll
            for (int mt = 0; mt < 4; ++mt) {
                float2 a0 = *(const float2*)(As + (wm + mt * 16 + qm)     * KPAD + kc);
                float2 a1 = *(const float2*)(As + (wm + mt * 16 + qm + 8) * KPAD + kc);
                af[mt][0] = __float_as_uint(a0.x);
                af[mt][1] = __float_as_uint(a1.x);
                af[mt][2] = __float_as_uint(a0.y);
                af[mt][3] = __float_as_uint(a1.y);
            }
            #pragma unroll
            for (int nt = 0; nt < 4; ++nt) {
                float2 bv = *(const float2*)(Bs + (wn + nt * 8 + qm) * KPAD + kc);
                bf[nt][0] = __float_as_uint(bv.x);
                bf[nt][1] = __float_as_uint(bv.y);
            }
            #pragma unroll
            for (int mt = 0; mt < 4; ++mt)
                #pragma unroll
                for (int nt = 0; nt < 4; ++nt)
                    mma_tf32(acc[mt][nt], af[mt], bf[nt]);
        }
        // NOTE: no trailing __syncthreads needed — buffer reuse is guarded by
        // the barrier at the top of the iteration that overwrites it.
    }

    #pragma unroll
    for (int mt = 0; mt < 4; ++mt) {
        const int r0 = m0 + wm + mt * 16 + qm;
        #pragma unroll
        for (int nt = 0; nt < 4; ++nt) {
            const int cc = n0 + wn + nt * 8 + 2 * qk;
            *(float2*)(C + (size_t)r0 * ldc + cc)       = make_float2(acc[mt][nt][0], acc[mt][nt][1]);
            *(float2*)(C + (size_t)(r0 + 8) * ldc + cc) = make_float2(acc[mt][nt][2], acc[mt][nt][3]);
        }
    }
}

// ---------------- canon conv + RMSNorm + RoPE + relayout (permute+round) ----
__global__ __launch_bounds__(256) void postproc_kernel(
    const float* __restrict__ qkv,
    const float* __restrict__ cwq, const float* __restrict__ cwk, const float* __restrict__ cwv,
    const float* __restrict__ qnw, const float* __restrict__ knw,
    const float2* __restrict__ rope,
    float* __restrict__ qo, float* __restrict__ ko, float* __restrict__ vo)
{
    __shared__ float sm[4096];
    const int s   = blockIdx.x;
    const int b   = blockIdx.y;
    const int tid = threadIdx.x;
    const float* row0 = qkv + ((size_t)b * S_ + s) * 4096;
    const float sc = 0.08838834764831845f;   // 1/sqrt(128), folded into Q

    for (int c = tid; c < 4096; c += 256) {
        const float* cw;
        if (c < 2048)       cw = cwq + (size_t)c * 4;
        else if (c < 3072)  cw = cwk + (size_t)(c - 2048) * 4;
        else                cw = cwv + (size_t)(c - 3072) * 4;
        float x0  = row0[c];
        float acc = x0 + cw[0] * x0;
        if (s >= 1) acc = fmaf(cw[1], row0[c - 4096],     acc);
        if (s >= 2) acc = fmaf(cw[2], row0[c - 2 * 4096], acc);
        if (s >= 3) acc = fmaf(cw[3], row0[c - 3 * 4096], acc);
        sm[c] = acc;
    }
    __syncthreads();

    // V: tf32-rounded copy (no permute — V's d-dim is the PV n-dim)
    for (int idx = tid; idx < KV_ * DH_; idx += 256) {
        int kvh = idx >> 7, d = idx & 127;
        vo[(((size_t)b * KV_ + kvh) * S_ + s) * DH_ + d] = rtf(sm[3072 + idx]);
    }

    const int warp = tid >> 5, lane = tid & 31;
    // permuted position for d = lane + 32*t (j = lane & 7 identical for all t)
    const int j  = lane & 7;
    const int pj = (j < 4) ? 2 * j : 2 * j - 7;
    const int p0 = (lane & ~7) + pj;

    const float2 cs0 = rope[(size_t)s * 64 + lane];
    const float2 cs1 = rope[(size_t)s * 64 + lane + 32];
    for (int h24 = warp; h24 < 24; h24 += 8) {
        bool isq  = h24 < 16;
        int  base = isq ? h24 * 128 : 2048 + (h24 - 16) * 128;
        float v0 = sm[base + lane];
        float v1 = sm[base + lane + 32];
        float v2 = sm[base + lane + 64];
        float v3 = sm[base + lane + 96];
        float ss = v0*v0 + v1*v1 + v2*v2 + v3*v3;
        #pragma unroll
        for (int o = 16; o > 0; o >>= 1) ss += __shfl_xor_sync(0xffffffffu, ss, o);
        float r = rsqrtf(ss * (1.0f / 128.0f) + 1e-6f);
        const float* nw = isq ? qnw : knw;
        float a0 = v0 * r * nw[lane];
        float a1 = v1 * r * nw[lane + 32];
        float a2 = v2 * r * nw[lane + 64];
        float a3 = v3 * r * nw[lane + 96];
        float o_lo0 = a0 * cs0.x - a2 * cs0.y;
        float o_hi0 = a2 * cs0.x + a0 * cs0.y;
        float o_lo1 = a1 * cs1.x - a3 * cs1.y;
        float o_hi1 = a3 * cs1.x + a1 * cs1.y;
        float* dst;
        float f = 1.0f;
        if (isq) { dst = qo + (((size_t)b * H_  + h24)        * S_ + s) * DH_; f = sc; }
        else     { dst = ko + (((size_t)b * KV_ + (h24 - 16)) * S_ + s) * DH_; }
        dst[p0]      = rtf(o_lo0 * f);
        dst[p0 + 32] = rtf(o_lo1 * f);
        dst[p0 + 64] = rtf(o_hi0 * f);
        dst[p0 + 96] = rtf(o_hi1 * f);
    }
}

// ---------------- causal flash attention, tf32 mma.sync ----------------------
#define FA_KS 136
#define FA_VS 136
#define FA_PS 72
#define FA_KTILE (64 * FA_KS)
#define FA_VTILE (64 * FA_VS)
#define FA_SMEM ((2 * FA_KTILE + 2 * FA_VTILE + 128 * FA_PS) * 4)

__global__ __launch_bounds__(256) void flash_mma_kernel(
    const float* __restrict__ Q, const float* __restrict__ Kg,
    const float* __restrict__ Vg, float* __restrict__ O)
{
    extern __shared__ float fs[];
    float* Ks0 = fs;
    float* Vs0 = fs + 2 * FA_KTILE;
    float* Ps  = fs + 2 * FA_KTILE + 2 * FA_VTILE;

    const int qblk = gridDim.x - 1 - blockIdx.x;
    const int q0   = qblk * 128;
    const int h    = blockIdx.y;
    const int b    = blockIdx.z;
    const int tid  = threadIdx.x;
    const int w    = tid >> 5, lane = tid & 31;
    const int qm   = lane >> 2, qk = lane & 3;
    const int wrow = w * 16;

    const float* Qb = Q  + (((size_t)b * H_  + h)        * S_ + q0 + wrow) * DH_;
    const float* Kb = Kg + (((size_t)b * KV_ + (h >> 1)) * S_) * DH_;
    const float* Vb = Vg + (((size_t)b * KV_ + (h >> 1)) * S_) * DH_;

    // Q fragments (pre-scaled, tf32, d-permuted) — float2 loads
    uint32_t qf[16][4];
    #pragma unroll
    for (int ks = 0; ks < 16; ++ks) {
        float2 q0v = *(const float2*)(Qb + (size_t)qm * DH_ + ks * 8 + 2 * qk);
        float2 q1v = *(const float2*)(Qb + (size_t)(qm + 8) * DH_ + ks * 8 + 2 * qk);
        qf[ks][0] = __float_as_uint(q0v.x);
        qf[ks][1] = __float_as_uint(q1v.x);
        qf[ks][2] = __float_as_uint(q0v.y);
        qf[ks][3] = __float_as_uint(q1v.y);
    }

    float o[16][4];
    #pragma unroll
    for (int nt = 0; nt < 16; ++nt)
        o[nt][0] = o[nt][1] = o[nt][2] = o[nt][3] = 0.f;
    float m0v = -1e30f, m1v = -1e30f, l0 = 0.f, l1 = 0.f;

    const int nb = 2 * (qblk + 1);
    const uint32_t ks_u = smem_u32(Ks0);
    const uint32_t vs_u = smem_u32(Vs0);

    auto prefetch = [&](int jb, int buf) {
        const int j0 = jb * 64;
        #pragma unroll
        for (int i = 0; i < 8; ++i) {
            int idx = tid + i * 256;
            int row = idx >> 5, c4 = idx & 31;
            cp_async16(ks_u + (uint32_t)(buf * FA_KTILE + row * FA_KS + c4 * 4) * 4,
                       Kb + (size_t)(j0 + row) * DH_ + c4 * 4);
            cp_async16(vs_u + (uint32_t)(buf * FA_VTILE + row * FA_VS + c4 * 4) * 4,
                       Vb + (size_t)(j0 + row) * DH_ + c4 * 4);
        }
        cp_commit();
    };

    prefetch(0, 0);

    for (int jb = 0; jb < nb; ++jb) {
        const int buf = jb & 1;
        const int j0  = jb * 64;

        __syncthreads();
        if (jb + 1 < nb) prefetch(jb + 1, buf ^ 1);
        else             cp_commit();
        cp_wait<1>();
        __syncthreads();

        const float* Kt = Ks0 + buf * FA_KTILE;
        const float* Vt = Vs0 + buf * FA_VTILE;

        // ---- S = Q K^T (K d-permuted -> float2 fragment loads) ----
        float sv[8][4];
        #pragma unroll
        for (int nt = 0; nt < 8; ++nt) {
            sv[nt][0] = sv[nt][1] = sv[nt][2] = sv[nt][3] = 0.f;
            const float* kp = Kt + (nt * 8 + qm) * FA_KS + 2 * qk;
            #pragma unroll
            for (int ks = 0; ks < 16; ++ks) {
                float2 kv = *(const float2*)(kp + ks * 8);
                uint32_t bfr[2];
                bfr[0] = __float_as_uint(kv.x);
                bfr[1] = __float_as_uint(kv.y);
                mma_tf32(sv[nt], qf[ks], bfr);
            }
        }

        // ---- causal mask (last two tiles only) ----
        if (jb >= nb - 2) {
            const int r0 = q0 + wrow + qm, r1 = r0 + 8;
            #pragma unroll
            for (int nt = 0; nt < 8; ++nt) {
                const int c0 = j0 + nt * 8 + 2 * qk;
                if (c0     > r0) sv[nt][0] = -1e30f;
                if (c0 + 1 > r0) sv[nt][1] = -1e30f;
                if (c0     > r1) sv[nt][2] = -1e30f;
                if (c0 + 1 > r1) sv[nt][3] = -1e30f;
            }
        }

        // ---- online softmax ----
        float mx0 = -1e30f, mx1 = -1e30f;
        #pragma unroll
        for (int nt = 0; nt < 8; ++nt) {
            mx0 = fmaxf(mx0, fmaxf(sv[nt][0], sv[nt][1]));
            mx1 = fmaxf(mx1, fmaxf(sv[nt][2], sv[nt][3]));
        }
        mx0 = fmaxf(mx0, __shfl_xor_sync(0xffffffffu, mx0, 1));
        mx0 = fmaxf(mx0, __shfl_xor_sync(0xffffffffu, mx0, 2));
        mx1 = fmaxf(mx1, __shfl_xor_sync(0xffffffffu, mx1, 1));
        mx1 = fmaxf(mx1, __shfl_xor_sync(0xffffffffu, mx1, 2));

        const float mn0 = fmaxf(m0v, mx0), mn1 = fmaxf(m1v, mx1);
        const float a0 = __expf(m0v - mn0), a1 = __expf(m1v - mn1);
        float rs0 = 0.f, rs1 = 0.f;

        float* prow0 = Ps + (wrow + qm) * FA_PS + 2 * qk;
        float* prow1 = prow0 + 8 * FA_PS;
        #pragma unroll
        for (int nt = 0; nt < 8; ++nt) {
            float p00 = __expf(sv[nt][0] - mn0);
            float p01 = __expf(sv[nt][1] - mn0);
            float p10 = __expf(sv[nt][2] - mn1);
            float p11 = __expf(sv[nt][3] - mn1);
            rs0 += p00 + p01;
            rs1 += p10 + p11;
            *(float2*)(prow0 + nt * 8) = make_float2(rtf(p00), rtf(p01));
            *(float2*)(prow1 + nt * 8) = make_float2(rtf(p10), rtf(p11));
        }
        rs0 += __shfl_xor_sync(0xffffffffu, rs0, 1);
        rs0 += __shfl_xor_sync(0xffffffffu, rs0, 2);
        rs1 += __shfl_xor_sync(0xffffffffu, rs1, 1);
        rs1 += __shfl_xor_sync(0xffffffffu, rs1, 2);

        l0 = l0 * a0 + rs0;  l1 = l1 * a1 + rs1;
        m0v = mn0;           m1v = mn1;
        #pragma unroll
        for (int nt = 0; nt < 16; ++nt) {
            o[nt][0] *= a0; o[nt][1] *= a0;
            o[nt][2] *= a1; o[nt][3] *= a1;
        }

        __syncwarp();   // P tile is warp-private: warp-level visibility suffices

        // ---- O += P V ----
        uint32_t aP[8][4];
        const float* pp = Ps + (wrow + qm) * FA_PS + qk;
        #pragma unroll
        for (int ks = 0; ks < 8; ++ks) {
            aP[ks][0] = __float_as_uint(pp[ks * 8]);
            aP[ks][1] = __float_as_uint(pp[8 * FA_PS + ks * 8]);
            aP[ks][2] = __float_as_uint(pp[ks * 8 + 4]);
            aP[ks][3] = __float_as_uint(pp[8 * FA_PS + ks * 8 + 4]);
        }
        #pragma unroll
        for (int nt = 0; nt < 16; ++nt) {
            const float* vp = Vt + qk * FA_VS + nt * 8 + qm;
            #pragma unroll
            for (int ks = 0; ks < 8; ++ks) {
                uint32_t bfr[2];
                bfr[0] = __float_as_uint(vp[(ks * 8)     * FA_VS]);
                bfr[1] = __float_as_uint(vp[(ks * 8 + 4) * FA_VS]);
                mma_tf32(o[nt], aP[ks], bfr);
            }
        }
    }

    // ---- epilogue: write tf32-rounded, d-permuted (for output GEMM) ----
    const float il0 = 1.f / l0, il1 = 1.f / l1;
    const int row0 = q0 + wrow + qm, row1 = row0 + 8;
    const int pos0 = (qk < 2) ? 4 * qk : 4 * qk - 7;   // perm pos of col 2qk
    const int pos1 = pos0 + 2;                          // perm pos of col 2qk+1
    float* O0 = O + ((size_t)b * S_ + row0) * D_ + h * DH_;
    float* O1 = O + ((size_t)b * S_ + row1) * D_ + h * DH_;
    #pragma unroll
    for (int nt = 0; nt < 16; ++nt) {
        O0[nt * 8 + pos0] = rtf(o[nt][0] * il0);
        O0[nt * 8 + pos1] = rtf(o[nt][1] * il0);
        O1[nt * 8 + pos0] = rtf(o[nt][2] * il1);
        O1[nt * 8 + pos1] = rtf(o[nt][3] * il1);
    }
}

// ---------------- launch ----------------
extern "C" void kernel_launch(void* const* d_in, const int* in_sizes, int n_in,
                              void* d_out, int out_size)
{
    const float* hidden = (const float*)d_in[0];
    const float* Wq     = (const float*)d_in[1];
    const float* Wk     = (const float*)d_in[2];
    const float* Wv     = (const float*)d_in[3];
    const float* Wo     = (const float*)d_in[4];
    const float* cwq    = (const float*)d_in[5];
    const float* cwk    = (const float*)d_in[6];
    const float* cwv    = (const float*)d_in[7];
    const float* qnw    = (const float*)d_in[8];
    const float* knw    = (const float*)d_in[9];
    float* out = (float*)d_out;

    float *qkv, *q, *k, *v, *attn, *hid, *wq, *wk, *wv, *wo;
    float2* rope;
    cudaGetSymbolAddress((void**)&qkv,  g_qkv);
    cudaGetSymbolAddress((void**)&q,    g_q);
    cudaGetSymbolAddress((void**)&k,    g_k);
    cudaGetSymbolAddress((void**)&v,    g_v);
    cudaGetSymbolAddress((void**)&attn, g_attn);
    cudaGetSymbolAddress((void**)&rope, g_rope);
    cudaGetSymbolAddress((void**)&hid,  g_hid);
    cudaGetSymbolAddress((void**)&wq,   g_wq);
    cudaGetSymbolAddress((void**)&wk,   g_wk);
    cudaGetSymbolAddress((void**)&wv,   g_wv);
    cudaGetSymbolAddress((void**)&wo,   g_wo);

    rope_init_kernel<<<(S_ * 64 + 255) / 256, 256>>>(rope);

    // tf32-round + k-permute operand copies
    permute_round_kernel<<<(B_*S_*D_/8 + 255)/256, 256>>>(hidden, hid, B_*S_*D_/8);
    permute_round_kernel<<<(D_*D_/8 + 255)/256, 256>>>(Wq, wq, D_*D_/8);
    permute_round_kernel<<<(1024*D_/8 + 255)/256, 256>>>(Wk, wk, 1024*D_/8);
    permute_round_kernel<<<(1024*D_/8 + 255)/256, 256>>>(Wv, wv, 1024*D_/8);
    permute_round_kernel<<<(D_*D_/8 + 255)/256, 256>>>(Wo, wo, D_*D_/8);

    cudaFuncSetAttribute(gemm_mma, cudaFuncAttributeMaxDynamicSharedMemorySize, GEMM_SMEM);

    // fused QKV projection: N = 4096 (q | k | v)
    gemm_mma<<<dim3(4096 / TN, (B_ * S_) / TM), 256, GEMM_SMEM>>>(
        hid, wq, wk, wv, qkv, 2048, 4096, 2048, 3072);

    postproc_kernel<<<dim3(S_, B_), 256>>>(qkv, cwq, cwk, cwv, qnw, knw, rope, q, k, v);

    cudaFuncSetAttribute(flash_mma_kernel, cudaFuncAttributeMaxDynamicSharedMemorySize, FA_SMEM);
    flash_mma_kernel<<<dim3(S_ / 128, H_, B_), 256, FA_SMEM>>>(q, k, v, attn);

    // output projection
    gemm_mma<<<dim3(D_ / TN, (B_ * S_) / TM), 256, GEMM_SMEM>>>(
        attn, wo, wo, wo, out, 2048, 2048, 1 << 30, 1 << 30);
}

// round 6
// speedup vs baseline: 3.9795x; 1.0510x over previous
#include <cuda_runtime.h>
#include <math.h>
#include <stdint.h>

#define B_   2
#define S_   2048
#define D_   2048
#define H_   16
#define KV_  8
#define DH_  128

// ---------------- persistent scratch ----------------
__device__ float  g_qkv [B_ * S_ * 4096];
__device__ float  g_q   [B_ * H_  * S_ * DH_];   // d-permuted, tf32, pre-scaled
__device__ float  g_k   [B_ * KV_ * S_ * DH_];   // d-permuted, tf32
__device__ float  g_v   [B_ * KV_ * S_ * DH_];   // tf32
__device__ float  g_attn[B_ * S_ * D_];          // d-permuted, tf32
__device__ float2 g_rope[S_ * 64];
__device__ float  g_hid [B_ * S_ * D_];
__device__ float  g_wq  [D_ * D_];
__device__ float  g_wk  [1024 * D_];
__device__ float  g_wv  [1024 * D_];
__device__ float  g_wo  [D_ * D_];

// ---------------- PTX helpers ----------------
__device__ __forceinline__ uint32_t smem_u32(const void* p) {
    uint32_t a;
    asm("{ .reg .u64 t; cvta.to.shared.u64 t, %1; cvt.u32.u64 %0, t; }" : "=r"(a) : "l"(p));
    return a;
}
__device__ __forceinline__ void cp_async16(uint32_t saddr, const void* gaddr) {
    asm volatile("cp.async.cg.shared.global [%0], [%1], 16;" :: "r"(saddr), "l"(gaddr));
}
__device__ __forceinline__ void cp_commit() {
    asm volatile("cp.async.commit_group;" ::: "memory");
}
template <int N>
__device__ __forceinline__ void cp_wait() {
    asm volatile("cp.async.wait_group %0;" :: "n"(N) : "memory");
}
__device__ __forceinline__ uint32_t f2tf32(float x) {
    uint32_t r;
    asm("cvt.rna.tf32.f32 %0, %1;" : "=r"(r) : "f"(x));
    return r;
}
__device__ __forceinline__ float rtf(float x) { return __uint_as_float(f2tf32(x)); }
__device__ __forceinline__ void mma_tf32(float* c, const uint32_t* a, const uint32_t* b) {
    asm volatile(
        "mma.sync.aligned.m16n8k8.row.col.f32.tf32.tf32.f32 "
        "{%0,%1,%2,%3}, {%4,%5,%6,%7}, {%8,%9}, {%0,%1,%2,%3};"
        : "+f"(c[0]), "+f"(c[1]), "+f"(c[2]), "+f"(c[3])
        : "r"(a[0]), "r"(a[1]), "r"(a[2]), "r"(a[3]), "r"(b[0]), "r"(b[1]));
}

// ---------------- prepass: tf32 round + k-permute [0,4,1,5,2,6,3,7] ---------
__global__ __launch_bounds__(256) void permute_round_kernel(
    const float* __restrict__ in, float* __restrict__ out, int ngroups)
{
    int g = blockIdx.x * blockDim.x + threadIdx.x;
    if (g >= ngroups) return;
    float4 a = ((const float4*)in)[2 * g];
    float4 b = ((const float4*)in)[2 * g + 1];
    float4 o0 = make_float4(rtf(a.x), rtf(b.x), rtf(a.y), rtf(b.y));
    float4 o1 = make_float4(rtf(a.z), rtf(b.z), rtf(a.w), rtf(b.w));
    ((float4*)out)[2 * g]     = o0;
    ((float4*)out)[2 * g + 1] = o1;
}

// ---------------- RoPE table ----------------
__global__ void rope_init_kernel(float2* __restrict__ tab) {
    int idx = blockIdx.x * blockDim.x + threadIdx.x;
    if (idx >= S_ * 64) return;
    int s = idx >> 6, j = idx & 63;
    double inv = exp(-(double)j * (9.210340371976184 / 64.0));
    double ang = (double)s * inv;
    tab[idx] = make_float2((float)cos(ang), (float)sin(ang));
}

// ---------------- mma.sync tf32 GEMM (k-permuted, pre-rounded inputs) --------
#define TM 128
#define TN 128
#define TK 16
#define KPAD 24
#define STAGE_FLOATS (2 * TM * KPAD)
#define STAGES 3
#define GEMM_SMEM (STAGES * STAGE_FLOATS * 4)

__global__ __launch_bounds__(256, 2) void gemm_mma(
    const float* __restrict__ A,
    const float* __restrict__ W0, const float* __restrict__ W1, const float* __restrict__ W2,
    float* __restrict__ C, int K, int ldc, int n1, int n2)
{
    extern __shared__ float smf[];
    const int tid  = threadIdx.x;
    const int wid  = tid >> 5, lane = tid & 31;
    const int qm   = lane >> 2, qk = lane & 3;
    const int m0   = blockIdx.y * TM;
    const int n0   = blockIdx.x * TN;
    const int wm   = (wid >> 2) * 64;
    const int wn   = (wid & 3) * 32;

    const float* W; int nr;
    if (n0 < n1)      { W = W0; nr = n0; }
    else if (n0 < n2) { W = W1; nr = n0 - n1; }
    else              { W = W2; nr = n0 - n2; }

    const float* Abase = A + (size_t)m0 * K;
    const float* Wbase = W + (size_t)nr * K;
    const uint32_t sb = smem_u32(smf);

    float acc[4][4][4];
    #pragma unroll
    for (int i = 0; i < 4; ++i)
        #pragma unroll
        for (int j = 0; j < 4; ++j)
            #pragma unroll
            for (int r = 0; r < 4; ++r) acc[i][j][r] = 0.f;

    const int NCH = K / TK;

    auto load_chunk = [&](int c, int buf) {
        const uint32_t abuf = sb + (uint32_t)buf * STAGE_FLOATS * 4;
        const uint32_t bbuf = abuf + TM * KPAD * 4;
        const int k0 = c * TK;
        #pragma unroll
        for (int i = 0; i < 2; ++i) {
            int idx = tid + i * 256;
            int row = idx >> 2, c4 = idx & 3;
            cp_async16(abuf + (uint32_t)(row * KPAD + c4 * 4) * 4,
                       Abase + (size_t)row * K + k0 + c4 * 4);
            cp_async16(bbuf + (uint32_t)(row * KPAD + c4 * 4) * 4,
                       Wbase + (size_t)row * K + k0 + c4 * 4);
        }
        cp_commit();
    };

    load_chunk(0, 0);
    load_chunk(1, 1);

    for (int c = 0; c < NCH; ++c) {
        if (c + 1 < NCH) cp_wait<1>();
        else             cp_wait<0>();
        __syncthreads();

        const int cn = c + STAGES - 1;
        if (cn < NCH) load_chunk(cn, cn % STAGES);

        const float* As = smf + (size_t)(c % STAGES) * STAGE_FLOATS;
        const float* Bs = As + TM * KPAD;

        #pragma unroll
        for (int ks = 0; ks < 2; ++ks) {
            const int kc = ks * 8 + 2 * qk;      // permuted pair (qk, qk+4)
            uint32_t af[4][4], bf[4][2];
            #pragma unroll
            for (int mt = 0; mt < 4; ++mt) {
                float2 a0 = *(const float2*)(As + (wm + mt * 16 + qm)     * KPAD + kc);
                float2 a1 = *(const float2*)(As + (wm + mt * 16 + qm + 8) * KPAD + kc);
                af[mt][0] = __float_as_uint(a0.x);
                af[mt][1] = __float_as_uint(a1.x);
                af[mt][2] = __float_as_uint(a0.y);
                af[mt][3] = __float_as_uint(a1.y);
            }
            #pragma unroll
            for (int nt = 0; nt < 4; ++nt) {
                float2 bv = *(const float2*)(Bs + (wn + nt * 8 + qm) * KPAD + kc);
                bf[nt][0] = __float_as_uint(bv.x);
                bf[nt][1] = __float_as_uint(bv.y);
            }
            #pragma unroll
            for (int mt = 0; mt < 4; ++mt)
                #pragma unroll
                for (int nt = 0; nt < 4; ++nt)
                    mma_tf32(acc[mt][nt], af[mt], bf[nt]);
        }
    }

    #pragma unroll
    for (int mt = 0; mt < 4; ++mt) {
        const int r0 = m0 + wm + mt * 16 + qm;
        #pragma unroll
        for (int nt = 0; nt < 4; ++nt) {
            const int cc = n0 + wn + nt * 8 + 2 * qk;
            *(float2*)(C + (size_t)r0 * ldc + cc)       = make_float2(acc[mt][nt][0], acc[mt][nt][1]);
            *(float2*)(C + (size_t)(r0 + 8) * ldc + cc) = make_float2(acc[mt][nt][2], acc[mt][nt][3]);
        }
    }
}

// ---------------- canon conv + RMSNorm + RoPE + relayout (permute+round) ----
__global__ __launch_bounds__(256) void postproc_kernel(
    const float* __restrict__ qkv,
    const float* __restrict__ cwq, const float* __restrict__ cwk, const float* __restrict__ cwv,
    const float* __restrict__ qnw, const float* __restrict__ knw,
    const float2* __restrict__ rope,
    float* __restrict__ qo, float* __restrict__ ko, float* __restrict__ vo)
{
    __shared__ float sm[4096];
    const int s   = blockIdx.x;
    const int b   = blockIdx.y;
    const int tid = threadIdx.x;
    const float* row0 = qkv + ((size_t)b * S_ + s) * 4096;
    const float sc = 0.08838834764831845f;

    for (int c = tid; c < 4096; c += 256) {
        const float* cw;
        if (c < 2048)       cw = cwq + (size_t)c * 4;
        else if (c < 3072)  cw = cwk + (size_t)(c - 2048) * 4;
        else                cw = cwv + (size_t)(c - 3072) * 4;
        float x0  = row0[c];
        float acc = x0 + cw[0] * x0;
        if (s >= 1) acc = fmaf(cw[1], row0[c - 4096],     acc);
        if (s >= 2) acc = fmaf(cw[2], row0[c - 2 * 4096], acc);
        if (s >= 3) acc = fmaf(cw[3], row0[c - 3 * 4096], acc);
        sm[c] = acc;
    }
    __syncthreads();

    // V: tf32-rounded copy
    for (int idx = tid; idx < KV_ * DH_; idx += 256) {
        int kvh = idx >> 7, d = idx & 127;
        vo[(((size_t)b * KV_ + kvh) * S_ + s) * DH_ + d] = rtf(sm[3072 + idx]);
    }

    const int warp = tid >> 5, lane = tid & 31;
    const int j  = lane & 7;
    const int pj = (j < 4) ? 2 * j : 2 * j - 7;
    const int p0 = (lane & ~7) + pj;

    const float2 cs0 = rope[(size_t)s * 64 + lane];
    const float2 cs1 = rope[(size_t)s * 64 + lane + 32];
    for (int h24 = warp; h24 < 24; h24 += 8) {
        bool isq  = h24 < 16;
        int  base = isq ? h24 * 128 : 2048 + (h24 - 16) * 128;
        float v0 = sm[base + lane];
        float v1 = sm[base + lane + 32];
        float v2 = sm[base + lane + 64];
        float v3 = sm[base + lane + 96];
        float ss = v0*v0 + v1*v1 + v2*v2 + v3*v3;
        #pragma unroll
        for (int o = 16; o > 0; o >>= 1) ss += __shfl_xor_sync(0xffffffffu, ss, o);
        float r = rsqrtf(ss * (1.0f / 128.0f) + 1e-6f);
        const float* nw = isq ? qnw : knw;
        float a0 = v0 * r * nw[lane];
        float a1 = v1 * r * nw[lane + 32];
        float a2 = v2 * r * nw[lane + 64];
        float a3 = v3 * r * nw[lane + 96];
        float o_lo0 = a0 * cs0.x - a2 * cs0.y;
        float o_hi0 = a2 * cs0.x + a0 * cs0.y;
        float o_lo1 = a1 * cs1.x - a3 * cs1.y;
        float o_hi1 = a3 * cs1.x + a1 * cs1.y;
        float* dst;
        float f = 1.0f;
        if (isq) { dst = qo + (((size_t)b * H_  + h24)        * S_ + s) * DH_; f = sc; }
        else     { dst = ko + (((size_t)b * KV_ + (h24 - 16)) * S_ + s) * DH_; }
        dst[p0]      = rtf(o_lo0 * f);
        dst[p0 + 32] = rtf(o_lo1 * f);
        dst[p0 + 64] = rtf(o_hi0 * f);
        dst[p0 + 96] = rtf(o_hi1 * f);
    }
}

// ---------------- causal flash attention, tf32 mma.sync ----------------------
// BM=128, BN=64. 3-buffer cp.async pipeline, ONE barrier per KV tile.
// P never touches smem: S C-fragments become PV A-fragments via V row
// permutation tau=[0,2,4,6,1,3,5,7] within each 8-seq group.
#define FA_KS 136
#define FA_TILE (64 * FA_KS)            // one K or V tile (floats)
#define FA_BUF  (2 * FA_TILE)           // K + V per stage
#define FA_SMEM (3 * FA_BUF * 4)        // 3 stages

__global__ __launch_bounds__(256) void flash_mma_kernel(
    const float* __restrict__ Q, const float* __restrict__ Kg,
    const float* __restrict__ Vg, float* __restrict__ O)
{
    extern __shared__ float fs[];

    const int qblk = gridDim.x - 1 - blockIdx.x;
    const int q0   = qblk * 128;
    const int h    = blockIdx.y;
    const int b    = blockIdx.z;
    const int tid  = threadIdx.x;
    const int w    = tid >> 5, lane = tid & 31;
    const int qm   = lane >> 2, qk = lane & 3;
    const int wrow = w * 16;

    const float* Qb = Q  + (((size_t)b * H_  + h)        * S_ + q0 + wrow) * DH_;
    const float* Kb = Kg + (((size_t)b * KV_ + (h >> 1)) * S_) * DH_;
    const float* Vb = Vg + (((size_t)b * KV_ + (h >> 1)) * S_) * DH_;

    // Q fragments (pre-scaled, tf32, d-permuted)
    uint32_t qf[16][4];
    #pragma unroll
    for (int ks = 0; ks < 16; ++ks) {
        float2 q0v = *(const float2*)(Qb + (size_t)qm * DH_ + ks * 8 + 2 * qk);
        float2 q1v = *(const float2*)(Qb + (size_t)(qm + 8) * DH_ + ks * 8 + 2 * qk);
        qf[ks][0] = __float_as_uint(q0v.x);
        qf[ks][1] = __float_as_uint(q1v.x);
        qf[ks][2] = __float_as_uint(q0v.y);
        qf[ks][3] = __float_as_uint(q1v.y);
    }

    float o[16][4];
    #pragma unroll
    for (int nt = 0; nt < 16; ++nt)
        o[nt][0] = o[nt][1] = o[nt][2] = o[nt][3] = 0.f;
    float m0v = -1e30f, m1v = -1e30f, l0 = 0.f, l1 = 0.f;

    const int nb = 2 * (qblk + 1);
    const uint32_t fs_u = smem_u32(fs);

    auto prefetch = [&](int jb, int buf) {
        const int j0 = jb * 64;
        const uint32_t kbuf = fs_u + (uint32_t)buf * FA_BUF * 4;
        const uint32_t vbuf = kbuf + FA_TILE * 4;
        #pragma unroll
        for (int i = 0; i < 8; ++i) {
            int idx = tid + i * 256;
            int row = idx >> 5, c4 = idx & 31;
            // K: natural row order
            cp_async16(kbuf + (uint32_t)(row * FA_KS + c4 * 4) * 4,
                       Kb + (size_t)(j0 + row) * DH_ + c4 * 4);
            // V: permute rows within 8-group (tau) so S-frag == PV A-frag
            int r8 = row & 7;
            int vsrc = (row & ~7) + ((r8 < 4) ? 2 * r8 : 2 * r8 - 7);
            cp_async16(vbuf + (uint32_t)(row * FA_KS + c4 * 4) * 4,
                       Vb + (size_t)(j0 + vsrc) * DH_ + c4 * 4);
        }
        cp_commit();
    };

    prefetch(0, 0);
    if (nb > 1) prefetch(1, 1);

    for (int jb = 0; jb < nb; ++jb) {
        const int buf = jb % 3;
        const int j0  = jb * 64;

        if (jb + 1 < nb) cp_wait<1>();
        else             cp_wait<0>();
        __syncthreads();                  // data visible + prior compute done

        if (jb + 2 < nb) prefetch(jb + 2, (jb + 2) % 3);

        const float* Kt = fs + (size_t)buf * FA_BUF;
        const float* Vt = Kt + FA_TILE;

        // ---- S = Q K^T ----
        float sv[8][4];
        #pragma unroll
        for (int nt = 0; nt < 8; ++nt) {
            sv[nt][0] = sv[nt][1] = sv[nt][2] = sv[nt][3] = 0.f;
            const float* kp = Kt + (nt * 8 + qm) * FA_KS + 2 * qk;
            #pragma unroll
            for (int ks = 0; ks < 16; ++ks) {
                float2 kv = *(const float2*)(kp + ks * 8);
                uint32_t bfr[2];
                bfr[0] = __float_as_uint(kv.x);
                bfr[1] = __float_as_uint(kv.y);
                mma_tf32(sv[nt], qf[ks], bfr);
            }
        }

        // ---- causal mask (last two tiles only) ----
        if (jb >= nb - 2) {
            const int r0 = q0 + wrow + qm, r1 = r0 + 8;
            #pragma unroll
            for (int nt = 0; nt < 8; ++nt) {
                const int c0 = j0 + nt * 8 + 2 * qk;
                if (c0     > r0) sv[nt][0] = -1e30f;
                if (c0 + 1 > r0) sv[nt][1] = -1e30f;
                if (c0     > r1) sv[nt][2] = -1e30f;
                if (c0 + 1 > r1) sv[nt][3] = -1e30f;
            }
        }

        // ---- online softmax (P stays in registers) ----
        float mx0 = -1e30f, mx1 = -1e30f;
        #pragma unroll
        for (int nt = 0; nt < 8; ++nt) {
            mx0 = fmaxf(mx0, fmaxf(sv[nt][0], sv[nt][1]));
            mx1 = fmaxf(mx1, fmaxf(sv[nt][2], sv[nt][3]));
        }
        mx0 = fmaxf(mx0, __shfl_xor_sync(0xffffffffu, mx0, 1));
        mx0 = fmaxf(mx0, __shfl_xor_sync(0xffffffffu, mx0, 2));
        mx1 = fmaxf(mx1, __shfl_xor_sync(0xffffffffu, mx1, 1));
        mx1 = fmaxf(mx1, __shfl_xor_sync(0xffffffffu, mx1, 2));

        const float mn0 = fmaxf(m0v, mx0), mn1 = fmaxf(m1v, mx1);
        const float a0 = __expf(m0v - mn0), a1 = __expf(m1v - mn1);
        float rs0 = 0.f, rs1 = 0.f;

        uint32_t aP[8][4];
        #pragma unroll
        for (int nt = 0; nt < 8; ++nt) {
            float p00 = __expf(sv[nt][0] - mn0);
            float p01 = __expf(sv[nt][1] - mn0);
            float p10 = __expf(sv[nt][2] - mn1);
            float p11 = __expf(sv[nt][3] - mn1);
            rs0 += p00 + p01;
            rs1 += p10 + p11;
            // A-frag for PV k-group nt: {P[qm][qk], P[qm+8][qk], P[qm][qk+4], P[qm+8][qk+4]}
            // == {p00, p10, p01, p11} thanks to the V row permutation.
            aP[nt][0] = f2tf32(p00);
            aP[nt][1] = f2tf32(p10);
            aP[nt][2] = f2tf32(p01);
            aP[nt][3] = f2tf32(p11);
        }
        rs0 += __shfl_xor_sync(0xffffffffu, rs0, 1);
        rs0 += __shfl_xor_sync(0xffffffffu, rs0, 2);
        rs1 += __shfl_xor_sync(0xffffffffu, rs1, 1);
        rs1 += __shfl_xor_sync(0xffffffffu, rs1, 2);

        l0 = l0 * a0 + rs0;  l1 = l1 * a1 + rs1;
        m0v = mn0;           m1v = mn1;
        #pragma unroll
        for (int nt = 0; nt < 16; ++nt) {
            o[nt][0] *= a0; o[nt][1] *= a0;
            o[nt][2] *= a1; o[nt][3] *= a1;
        }

        // ---- O += P V (A-frags in registers) ----
        #pragma unroll
        for (int nt = 0; nt < 16; ++nt) {
            const float* vp = Vt + qk * FA_KS + nt * 8 + qm;
            #pragma unroll
            for (int ks = 0; ks < 8; ++ks) {
                uint32_t bfr[2];
                bfr[0] = __float_as_uint(vp[(ks * 8)     * FA_KS]);
                bfr[1] = __float_as_uint(vp[(ks * 8 + 4) * FA_KS]);
                mma_tf32(o[nt], aP[ks], bfr);
            }
        }
    }

    // ---- epilogue: tf32-rounded, d-permuted (for output GEMM) ----
    const float il0 = 1.f / l0, il1 = 1.f / l1;
    const int row0 = q0 + wrow + qm, row1 = row0 + 8;
    const int pos0 = (qk < 2) ? 4 * qk : 4 * qk - 7;
    const int pos1 = pos0 + 2;
    float* O0 = O + ((size_t)b * S_ + row0) * D_ + h * DH_;
    float* O1 = O + ((size_t)b * S_ + row1) * D_ + h * DH_;
    #pragma unroll
    for (int nt = 0; nt < 16; ++nt) {
        O0[nt * 8 + pos0] = rtf(o[nt][0] * il0);
        O0[nt * 8 + pos1] = rtf(o[nt][1] * il0);
        O1[nt * 8 + pos0] = rtf(o[nt][2] * il1);
        O1[nt * 8 + pos1] = rtf(o[nt][3] * il1);
    }
}

// ---------------- launch ----------------
extern "C" void kernel_launch(void* const* d_in, const int* in_sizes, int n_in,
                              void* d_out, int out_size)
{
    const float* hidden = (const float*)d_in[0];
    const float* Wq     = (const float*)d_in[1];
    const float* Wk     = (const float*)d_in[2];
    const float* Wv     = (const float*)d_in[3];
    const float* Wo     = (const float*)d_in[4];
    const float* cwq    = (const float*)d_in[5];
    const float* cwk    = (const float*)d_in[6];
    const float* cwv    = (const float*)d_in[7];
    const float* qnw    = (const float*)d_in[8];
    const float* knw    = (const float*)d_in[9];
    float* out = (float*)d_out;

    float *qkv, *q, *k, *v, *attn, *hid, *wq, *wk, *wv, *wo;
    float2* rope;
    cudaGetSymbolAddress((void**)&qkv,  g_qkv);
    cudaGetSymbolAddress((void**)&q,    g_q);
    cudaGetSymbolAddress((void**)&k,    g_k);
    cudaGetSymbolAddress((void**)&v,    g_v);
    cudaGetSymbolAddress((void**)&attn, g_attn);
    cudaGetSymbolAddress((void**)&rope, g_rope);
    cudaGetSymbolAddress((void**)&hid,  g_hid);
    cudaGetSymbolAddress((void**)&wq,   g_wq);
    cudaGetSymbolAddress((void**)&wk,   g_wk);
    cudaGetSymbolAddress((void**)&wv,   g_wv);
    cudaGetSymbolAddress((void**)&wo,   g_wo);

    rope_init_kernel<<<(S_ * 64 + 255) / 256, 256>>>(rope);

    permute_round_kernel<<<(B_*S_*D_/8 + 255)/256, 256>>>(hidden, hid, B_*S_*D_/8);
    permute_round_kernel<<<(D_*D_/8 + 255)/256, 256>>>(Wq, wq, D_*D_/8);
    permute_round_kernel<<<(1024*D_/8 + 255)/256, 256>>>(Wk, wk, 1024*D_/8);
    permute_round_kernel<<<(1024*D_/8 + 255)/256, 256>>>(Wv, wv, 1024*D_/8);
    permute_round_kernel<<<(D_*D_/8 + 255)/256, 256>>>(Wo, wo, D_*D_/8);

    cudaFuncSetAttribute(gemm_mma, cudaFuncAttributeMaxDynamicSharedMemorySize, GEMM_SMEM);

    gemm_mma<<<dim3(4096 / TN, (B_ * S_) / TM), 256, GEMM_SMEM>>>(
        hid, wq, wk, wv, qkv, 2048, 4096, 2048, 3072);

    postproc_kernel<<<dim3(S_, B_), 256>>>(qkv, cwq, cwk, cwv, qnw, knw, rope, q, k, v);

    cudaFuncSetAttribute(flash_mma_kernel, cudaFuncAttributeMaxDynamicSharedMemorySize, FA_SMEM);
    flash_mma_kernel<<<dim3(S_ / 128, H_, B_), 256, FA_SMEM>>>(q, k, v, attn);

    gemm_mma<<<dim3(D_ / TN, (B_ * S_) / TM), 256, GEMM_SMEM>>>(
        attn, wo, wo, wo, out, 2048, 2048, 1 << 30, 1 << 30);
}